// round 1
// baseline (speedup 1.0000x reference)
#include <cuda_runtime.h>

#define NUM_TOKENS 4096
#define NUM_EXPERTS 16
#define HIDDEN 2880
#define INTER 2880
#define N1 (2 * INTER)          /* 5760 */
#define ROWS (NUM_TOKENS * 2)   /* 8192 expanded rows (top-2) */

// ---------------- scratch (device globals; no runtime allocation) ----------
__device__ float g_h13[(size_t)ROWS * N1];     // GEMM1 output (gate|up), ~189MB
__device__ float g_act[(size_t)ROWS * INTER];  // silu(gate)*up, ~94MB
__device__ float g_y[(size_t)ROWS * HIDDEN];   // GEMM2 output, ~94MB
__device__ int   g_rowmap[ROWS];               // compact row -> token id
__device__ int   g_row_of[NUM_TOKENS * 2];     // (token,k) -> compact row
__device__ float g_gate_of[NUM_TOKENS * 2];    // (token,k) -> gate weight
__device__ int   g_expert_of[NUM_TOKENS * 2];  // (token,k) -> expert
__device__ int   g_counts[NUM_EXPERTS];
__device__ int   g_offsets[NUM_EXPERTS + 1];
__device__ int   g_cursor[NUM_EXPERTS];

// ---------------- routing ---------------------------------------------------
__global__ void k_init() {
    int i = threadIdx.x;
    if (i < NUM_EXPERTS) { g_counts[i] = 0; g_cursor[i] = 0; }
}

__global__ void k_route(const float* __restrict__ logits) {
    int t = blockIdx.x * blockDim.x + threadIdx.x;
    if (t >= NUM_TOKENS) return;
    const float* l = logits + (size_t)t * NUM_EXPERTS;
    float v[NUM_EXPERTS];
#pragma unroll
    for (int e = 0; e < NUM_EXPERTS; e++) v[e] = l[e];
    int i1 = 0; float v1 = v[0];
#pragma unroll
    for (int e = 1; e < NUM_EXPERTS; e++) if (v[e] > v1) { v1 = v[e]; i1 = e; }
    int i2 = -1; float v2 = -1e30f;
#pragma unroll
    for (int e = 0; e < NUM_EXPERTS; e++)
        if (e != i1 && v[e] > v2) { v2 = v[e]; i2 = e; }
    // top-2 softmax renormalized: g1 = exp(v1)/(exp(v1)+exp(v2))
    float g1 = 1.0f / (1.0f + expf(v2 - v1));
    float g2 = 1.0f - g1;
    g_expert_of[2 * t + 0] = i1;  g_gate_of[2 * t + 0] = g1;
    g_expert_of[2 * t + 1] = i2;  g_gate_of[2 * t + 1] = g2;
    atomicAdd(&g_counts[i1], 1);
    atomicAdd(&g_counts[i2], 1);
}

__global__ void k_scan() {
    // single thread: 16-element exclusive scan
    if (threadIdx.x == 0) {
        int acc = 0;
        for (int e = 0; e < NUM_EXPERTS; e++) {
            g_offsets[e] = acc;
            acc += g_counts[e];
        }
        g_offsets[NUM_EXPERTS] = acc;  // == ROWS
    }
}

__global__ void k_scatter() {
    int t = blockIdx.x * blockDim.x + threadIdx.x;
    if (t >= NUM_TOKENS) return;
#pragma unroll
    for (int k = 0; k < 2; k++) {
        int e = g_expert_of[2 * t + k];
        int pos = g_offsets[e] + atomicAdd(&g_cursor[e], 1);
        g_rowmap[pos] = t;
        g_row_of[2 * t + k] = pos;
    }
}

// ---------------- tiled fp32 GEMM: C[r,n] = sum_k A[r,k]*W[e][n,k] + bias ---
// mode==1: A = hidden_states with gather via g_rowmap, C = g_h13 (ldc=N1)
// mode==2: A = g_act (compact rows),               C = g_y   (ldc=HIDDEN)
#define BM 128
#define BN 128
#define BKK 16

__global__ __launch_bounds__(256, 1) void k_gemm(
    const float* __restrict__ Aext,
    const float* __restrict__ W,
    const float* __restrict__ bias,
    int N, int ldc, int mode)
{
    const int K = HIDDEN;  // 2880 for both GEMMs
    int e = blockIdx.z;
    int seg0 = g_offsets[e];
    int cnt  = g_offsets[e + 1] - seg0;
    int m0 = blockIdx.y * BM;
    if (m0 >= cnt) return;
    int n0 = blockIdx.x * BN;

    const float* A = (mode == 1) ? Aext : g_act;
    float* C = (mode == 1) ? g_h13 : g_y;
    const int* rowmap = (mode == 1) ? g_rowmap : nullptr;

    __shared__ float As[BKK][BM];
    __shared__ float Bs[BKK][BN];

    int tid = threadIdx.x;
    int tx = tid & 15;       // col group
    int ty = tid >> 4;       // row group

    const float* Wp = W + (size_t)e * N * K;
    const float* be = bias + (size_t)e * N;

    // each thread loads 2 float4 of A and 2 float4 of B per K-tile
    const float* aptr[2]; bool aval[2]; int ar[2], akk[2];
    const float* bptr[2]; bool bval[2]; int br[2], bkk[2];
#pragma unroll
    for (int i = 0; i < 2; i++) {
        int slot = tid * 2 + i;            // 0..511
        int r  = slot >> 2;                // 0..127
        int kk = (slot & 3) * 4;           // 0,4,8,12
        ar[i] = r; akk[i] = kk;
        int m = m0 + r;
        aval[i] = (m < cnt);
        int grow = 0;
        if (aval[i]) grow = rowmap ? rowmap[seg0 + m] : (seg0 + m);
        aptr[i] = A + (size_t)grow * K + kk;
        br[i] = r; bkk[i] = kk;
        int n = n0 + r;
        bval[i] = (n < N);
        bptr[i] = Wp + (size_t)(bval[i] ? n : 0) * K + kk;
    }

    float acc[8][8];
#pragma unroll
    for (int i = 0; i < 8; i++)
#pragma unroll
        for (int j = 0; j < 8; j++) acc[i][j] = 0.0f;

    for (int kt = 0; kt < K / BKK; kt++) {
#pragma unroll
        for (int i = 0; i < 2; i++) {
            float4 va = aval[i] ? *(const float4*)aptr[i] : make_float4(0, 0, 0, 0);
            aptr[i] += BKK;
            As[akk[i] + 0][ar[i]] = va.x;
            As[akk[i] + 1][ar[i]] = va.y;
            As[akk[i] + 2][ar[i]] = va.z;
            As[akk[i] + 3][ar[i]] = va.w;
            float4 vb = bval[i] ? *(const float4*)bptr[i] : make_float4(0, 0, 0, 0);
            bptr[i] += BKK;
            Bs[bkk[i] + 0][br[i]] = vb.x;
            Bs[bkk[i] + 1][br[i]] = vb.y;
            Bs[bkk[i] + 2][br[i]] = vb.z;
            Bs[bkk[i] + 3][br[i]] = vb.w;
        }
        __syncthreads();
#pragma unroll
        for (int k = 0; k < BKK; k++) {
            float ra[8], rb[8];
            *(float4*)&ra[0] = *(const float4*)&As[k][ty * 8];
            *(float4*)&ra[4] = *(const float4*)&As[k][ty * 8 + 4];
            *(float4*)&rb[0] = *(const float4*)&Bs[k][tx * 8];
            *(float4*)&rb[4] = *(const float4*)&Bs[k][tx * 8 + 4];
#pragma unroll
            for (int i = 0; i < 8; i++)
#pragma unroll
                for (int j = 0; j < 8; j++)
                    acc[i][j] += ra[i] * rb[j];
        }
        __syncthreads();
    }

    // epilogue: +bias, guarded stores (float4, N % 4 == 0)
#pragma unroll
    for (int i = 0; i < 8; i++) {
        int m = m0 + ty * 8 + i;
        if (m >= cnt) break;
        size_t crow = (size_t)(seg0 + m) * ldc;
#pragma unroll
        for (int j4 = 0; j4 < 2; j4++) {
            int n = n0 + tx * 8 + j4 * 4;
            if (n < N) {
                float4 o;
                o.x = acc[i][j4 * 4 + 0] + be[n + 0];
                o.y = acc[i][j4 * 4 + 1] + be[n + 1];
                o.z = acc[i][j4 * 4 + 2] + be[n + 2];
                o.w = acc[i][j4 * 4 + 3] + be[n + 3];
                *(float4*)&C[crow + n] = o;
            }
        }
    }
}

// ---------------- SiLU(gate) * up -------------------------------------------
__global__ void k_silu() {
    int idx = blockIdx.x * blockDim.x + threadIdx.x;   // over ROWS*INTER/4
    const int per_row = INTER / 4;
    if (idx >= ROWS * per_row) return;
    int row = idx / per_row;
    int jq  = idx - row * per_row;
    const float4 g = *((const float4*)(g_h13 + (size_t)row * N1) + jq);
    const float4 u = *((const float4*)(g_h13 + (size_t)row * N1 + INTER) + jq);
    float4 r;
    r.x = g.x / (1.0f + expf(-g.x)) * u.x;
    r.y = g.y / (1.0f + expf(-g.y)) * u.y;
    r.z = g.z / (1.0f + expf(-g.z)) * u.z;
    r.w = g.w / (1.0f + expf(-g.w)) * u.w;
    ((float4*)g_act)[idx] = r;
}

// ---------------- final combine: out[t] = g1*y[r1] + g2*y[r2] ---------------
__global__ void k_combine(float* __restrict__ out) {
    int idx = blockIdx.x * blockDim.x + threadIdx.x;   // over NUM_TOKENS*HIDDEN/4
    const int per_row = HIDDEN / 4;
    if (idx >= NUM_TOKENS * per_row) return;
    int t  = idx / per_row;
    int hq = idx - t * per_row;
    int r1 = g_row_of[2 * t + 0];
    int r2 = g_row_of[2 * t + 1];
    float g1 = g_gate_of[2 * t + 0];
    float g2 = g_gate_of[2 * t + 1];
    float4 a = *((const float4*)(g_y + (size_t)r1 * HIDDEN) + hq);
    float4 b = *((const float4*)(g_y + (size_t)r2 * HIDDEN) + hq);
    float4 o;
    o.x = g1 * a.x + g2 * b.x;
    o.y = g1 * a.y + g2 * b.y;
    o.z = g1 * a.z + g2 * b.z;
    o.w = g1 * a.w + g2 * b.w;
    ((float4*)out)[idx] = o;
}

// ---------------- launch -----------------------------------------------------
extern "C" void kernel_launch(void* const* d_in, const int* in_sizes, int n_in,
                              void* d_out, int out_size)
{
    const float* hs   = (const float*)d_in[0];  // (4096, 2880)
    const float* rl   = (const float*)d_in[1];  // (4096, 16)
    const float* w13  = (const float*)d_in[2];  // (16, 5760, 2880)
    const float* w2   = (const float*)d_in[3];  // (16, 2880, 2880)
    const float* w13b = (const float*)d_in[4];  // (16, 5760)
    const float* w2b  = (const float*)d_in[5];  // (16, 2880)
    float* out = (float*)d_out;                 // (4096, 2880)

    k_init<<<1, 32>>>();
    k_route<<<(NUM_TOKENS + 255) / 256, 256>>>(rl);
    k_scan<<<1, 1>>>();
    k_scatter<<<(NUM_TOKENS + 255) / 256, 256>>>();

    // GEMM1: h13 = gather(hs) @ w13^T + w13_bias      (N = 5760)
    {
        dim3 grid(N1 / BN, (NUM_TOKENS + BM - 1) / BM, NUM_EXPERTS);
        k_gemm<<<grid, 256>>>(hs, w13, w13b, N1, N1, /*mode=*/1);
    }

    // SiLU(gate) * up
    {
        int total = ROWS * (INTER / 4);
        k_silu<<<(total + 255) / 256, 256>>>();
    }

    // GEMM2: y = act @ w2^T + w2_bias                 (N = 2880)
    {
        dim3 grid((HIDDEN + BN - 1) / BN, (NUM_TOKENS + BM - 1) / BM, NUM_EXPERTS);
        k_gemm<<<grid, 256>>>(nullptr, w2, w2b, HIDDEN, HIDDEN, /*mode=*/2);
    }

    // combine with gates
    {
        int total = NUM_TOKENS * (HIDDEN / 4);
        k_combine<<<(total + 255) / 256, 256>>>(out);
    }
}

// round 4
// speedup vs baseline: 5.0123x; 5.0123x over previous
#include <cuda_runtime.h>
#include <cuda_fp16.h>
#include <cstdint>

#define NUM_TOKENS 4096
#define NUM_EXPERTS 16
#define HIDDEN 2880
#define INTER 2880
#define N1 (2 * INTER)          /* 5760 */
#define ROWS (NUM_TOKENS * 2)   /* 8192 expanded rows */

#define BM 128
#define BN 64                   /* N tile (per gate/up in GEMM1) */
#define BK 32                   /* K chunk, halves */
#define NC (HIDDEN / BK)        /* 90 k-iterations */
#define NT (INTER / BN)         /* 45 N tiles */
#define MAXMT (ROWS / BM)       /* 64 */

#define PITCHB 80               /* smem row pitch in bytes (32 halves + 16B pad) */
#define A_BYTES (BM * PITCHB)   /* 10240 */
#define B_BYTES (BN * PITCHB)   /* 5120  */
#define STG1 (A_BYTES + 2 * B_BYTES)  /* 20480: A | Bg | Bu */
#define STG2 (A_BYTES + B_BYTES)      /* 15360: A | B */
#define G1_SMEM (1024 + 3 * STG1)
#define G2_SMEM (1024 + 3 * STG2)

// ---------------- device scratch ----------------------------------------------
__device__ __align__(256) __half g_w13h[(size_t)NUM_EXPERTS * N1 * HIDDEN];
__device__ __align__(256) __half g_w2h[(size_t)NUM_EXPERTS * HIDDEN * INTER];
__device__ __align__(256) __half g_hsh[(size_t)NUM_TOKENS * HIDDEN];
__device__ __align__(256) __half g_acth[(size_t)ROWS * INTER];
__device__ __align__(256) float  g_y[(size_t)ROWS * HIDDEN];
__device__ int   g_rowmap[ROWS];
__device__ int   g_row_of[NUM_TOKENS * 2];
__device__ float g_gate_of[NUM_TOKENS * 2];
__device__ int   g_expert_of[NUM_TOKENS * 2];
__device__ int   g_counts[NUM_EXPERTS];
__device__ int   g_offsets[NUM_EXPERTS + 1];
__device__ int   g_cursor[NUM_EXPERTS];

// ---------------- helpers ------------------------------------------------------
__device__ __forceinline__ uint32_t h2u(float a, float b) {
    __half2 h = __floats2half2_rn(a, b);
    return *reinterpret_cast<uint32_t*>(&h);
}
__device__ __forceinline__ uint32_t smem_u32(const void* p) {
    uint32_t a;
    asm("{ .reg .u64 t; cvta.to.shared.u64 t, %1; cvt.u32.u64 %0, t; }"
        : "=r"(a) : "l"(p));
    return a;
}
#define CP16(dst, src) \
    asm volatile("cp.async.cg.shared.global [%0], [%1], 16;" :: "r"(dst), "l"(src))
#define CP_COMMIT() asm volatile("cp.async.commit_group;" ::: "memory")
#define CP_WAIT2()  asm volatile("cp.async.wait_group 2;" ::: "memory")

__device__ __forceinline__ void ldsm4(uint32_t& r0, uint32_t& r1, uint32_t& r2,
                                      uint32_t& r3, uint32_t addr) {
    asm volatile("ldmatrix.sync.aligned.m8n8.x4.shared.b16 {%0,%1,%2,%3}, [%4];"
                 : "=r"(r0), "=r"(r1), "=r"(r2), "=r"(r3) : "r"(addr));
}
__device__ __forceinline__ void mma16816(float* c, uint32_t a0, uint32_t a1,
                                         uint32_t a2, uint32_t a3,
                                         uint32_t b0, uint32_t b1) {
    asm volatile(
        "mma.sync.aligned.m16n8k16.row.col.f32.f16.f16.f32 "
        "{%0,%1,%2,%3}, {%4,%5,%6,%7}, {%8,%9}, {%0,%1,%2,%3};"
        : "+f"(c[0]), "+f"(c[1]), "+f"(c[2]), "+f"(c[3])
        : "r"(a0), "r"(a1), "r"(a2), "r"(a3), "r"(b0), "r"(b1));
}
__device__ __forceinline__ float silu(float x) {
    return x / (1.0f + expf(-x));
}

// ---------------- routing ----------------------------------------------------
__global__ void k_init() {
    int i = threadIdx.x;
    if (i < NUM_EXPERTS) { g_counts[i] = 0; g_cursor[i] = 0; }
}
__global__ void k_route(const float* __restrict__ logits) {
    int t = blockIdx.x * blockDim.x + threadIdx.x;
    if (t >= NUM_TOKENS) return;
    const float* l = logits + (size_t)t * NUM_EXPERTS;
    float v[NUM_EXPERTS];
#pragma unroll
    for (int e = 0; e < NUM_EXPERTS; e++) v[e] = l[e];
    int i1 = 0; float v1 = v[0];
#pragma unroll
    for (int e = 1; e < NUM_EXPERTS; e++) if (v[e] > v1) { v1 = v[e]; i1 = e; }
    int i2 = -1; float v2 = -1e30f;
#pragma unroll
    for (int e = 0; e < NUM_EXPERTS; e++)
        if (e != i1 && v[e] > v2) { v2 = v[e]; i2 = e; }
    float g1 = 1.0f / (1.0f + expf(v2 - v1));
    g_expert_of[2 * t + 0] = i1;  g_gate_of[2 * t + 0] = g1;
    g_expert_of[2 * t + 1] = i2;  g_gate_of[2 * t + 1] = 1.0f - g1;
    atomicAdd(&g_counts[i1], 1);
    atomicAdd(&g_counts[i2], 1);
}
__global__ void k_scan() {
    if (threadIdx.x == 0) {
        int acc = 0;
        for (int e = 0; e < NUM_EXPERTS; e++) { g_offsets[e] = acc; acc += g_counts[e]; }
        g_offsets[NUM_EXPERTS] = acc;
    }
}
__global__ void k_scatter() {
    int t = blockIdx.x * blockDim.x + threadIdx.x;
    if (t >= NUM_TOKENS) return;
#pragma unroll
    for (int k = 0; k < 2; k++) {
        int e = g_expert_of[2 * t + k];
        int pos = g_offsets[e] + atomicAdd(&g_cursor[e], 1);
        g_rowmap[pos] = t;
        g_row_of[2 * t + k] = pos;
    }
}

// ---------------- fp32 -> fp16 -------------------------------------------------
__global__ void k_cvt(const float4* __restrict__ src, uint2* __restrict__ dst,
                      size_t n4) {
    size_t i = (size_t)blockIdx.x * blockDim.x + threadIdx.x;
    if (i >= n4) return;
    float4 v = src[i];
    uint2 o;
    o.x = h2u(v.x, v.y);
    o.y = h2u(v.z, v.w);
    dst[i] = o;
}

// ---------------- GEMM1: act = silu(X@Wg^T+bg) * (X@Wu^T+bu) -------------------
// smem: [0:512) stok int[128] | [512:1024) sbias float[128] | [1024+): 3 stages
__global__ __launch_bounds__(256, 2) void k_gemm1(const float* __restrict__ w13b) {
    extern __shared__ __align__(128) uint8_t smem[];
    int* stok = (int*)smem;
    float* sbias = (float*)(smem + 512);
    uint32_t sb = smem_u32(smem);
    uint32_t stage0 = sb + 1024;

    int e = blockIdx.z;
    int seg0 = g_offsets[e];
    int cnt  = g_offsets[e + 1] - seg0;
    int m0 = blockIdx.y * BM;
    if (m0 >= cnt) return;
    int n0 = blockIdx.x * BN;
    int tid = threadIdx.x, wid = tid >> 5, lid = tid & 31;
    int warpM = wid & 3, warpN = wid >> 2;

    // per-CTA token map + bias
    if (tid < BM) {
        int m = m0 + tid;
        stok[tid] = g_rowmap[seg0 + (m < cnt ? m : cnt - 1)];
    }
    if (tid >= 128 && tid < 192)
        sbias[tid - 128] = w13b[(size_t)e * N1 + n0 + (tid - 128)];
    else if (tid >= 192)
        sbias[tid - 192 + 64] = w13b[(size_t)e * N1 + INTER + n0 + (tid - 192)];
    __syncthreads();

    const __half* wg = g_w13h + (size_t)e * N1 * HIDDEN + (size_t)n0 * HIDDEN;
    const __half* wu = g_w13h + (size_t)e * N1 * HIDDEN + (size_t)(INTER + n0) * HIDDEN;

    // ---- async load of one k-chunk into a stage -------------------------------
    auto load_stage = [&](int s, int c) {
        uint32_t st = stage0 + s * STG1;
        int k0 = c * BK;
#pragma unroll
        for (int q = 0; q < 4; q++) {
            int ch = tid + q * 256;          // 0..1023
            if (ch < 512) {                  // A: 128 rows x 4 chunks
                int r = ch >> 2, c4 = ch & 3;
                const __half* src = g_hsh + (size_t)stok[r] * HIDDEN + k0 + c4 * 8;
                CP16(st + r * PITCHB + c4 * 16, src);
            } else if (ch < 768) {           // Bg: 64 rows x 4 chunks
                int i = ch - 512, r = i >> 2, c4 = i & 3;
                const __half* src = wg + (size_t)r * HIDDEN + k0 + c4 * 8;
                CP16(st + A_BYTES + r * PITCHB + c4 * 16, src);
            } else {                         // Bu
                int i = ch - 768, r = i >> 2, c4 = i & 3;
                const __half* src = wu + (size_t)r * HIDDEN + k0 + c4 * 8;
                CP16(st + A_BYTES + B_BYTES + r * PITCHB + c4 * 16, src);
            }
        }
        CP_COMMIT();
    };

    float accG[2][4][4], accU[2][4][4];
#pragma unroll
    for (int i = 0; i < 2; i++)
#pragma unroll
        for (int j = 0; j < 4; j++)
#pragma unroll
            for (int q = 0; q < 4; q++) { accG[i][j][q] = 0.f; accU[i][j][q] = 0.f; }

    load_stage(0, 0);
    load_stage(1, 1);
    load_stage(2, 2);

    // lane addressing for ldmatrix (row = lane&15, col8 = (lane&16)? 8 halves : 0)
    int lrow = lid & 15;
    int lcolb = (lid & 16);                  // 0 or 16 bytes

    for (int c = 0; c < NC; c++) {
        CP_WAIT2();
        __syncthreads();
        uint32_t st = stage0 + (c % 3) * STG1;
        uint32_t aBase = st + (warpM * 32 + lrow) * PITCHB + lcolb;
        uint32_t gBase = st + A_BYTES + (warpN * 32 + lrow) * PITCHB + lcolb;
        uint32_t uBase = gBase + B_BYTES;
#pragma unroll
        for (int kk = 0; kk < 2; kk++) {     // two k16 steps
            uint32_t koff = kk * 32;         // 16 halves = 32 bytes
            uint32_t a[2][4];
            ldsm4(a[0][0], a[0][1], a[0][2], a[0][3], aBase + koff);
            ldsm4(a[1][0], a[1][1], a[1][2], a[1][3], aBase + 16 * PITCHB + koff);
#pragma unroll
            for (int ntp = 0; ntp < 2; ntp++) {
                uint32_t b0, b1, b2, b3;
                ldsm4(b0, b1, b2, b3, gBase + ntp * 16 * PITCHB + koff);
#pragma unroll
                for (int mt = 0; mt < 2; mt++) {
                    mma16816(accG[mt][2 * ntp + 0], a[mt][0], a[mt][1], a[mt][2], a[mt][3], b0, b2);
                    mma16816(accG[mt][2 * ntp + 1], a[mt][0], a[mt][1], a[mt][2], a[mt][3], b1, b3);
                }
                ldsm4(b0, b1, b2, b3, uBase + ntp * 16 * PITCHB + koff);
#pragma unroll
                for (int mt = 0; mt < 2; mt++) {
                    mma16816(accU[mt][2 * ntp + 0], a[mt][0], a[mt][1], a[mt][2], a[mt][3], b0, b2);
                    mma16816(accU[mt][2 * ntp + 1], a[mt][0], a[mt][1], a[mt][2], a[mt][3], b1, b3);
                }
            }
        }
        __syncthreads();
        if (c + 3 < NC) load_stage(c % 3, c + 3);
        else CP_COMMIT();
    }

    // ---- fused bias + SiLU*up epilogue -> fp16 act -----------------------------
    int g = lid >> 2, t = lid & 3;
#pragma unroll
    for (int mt = 0; mt < 2; mt++) {
#pragma unroll
        for (int nt = 0; nt < 4; nt++) {
            int ncol = warpN * 32 + nt * 8 + 2 * t;            // within [0,64)
            float bg0 = sbias[ncol], bg1 = sbias[ncol + 1];
            float bu0 = sbias[64 + ncol], bu1 = sbias[64 + ncol + 1];
            int mA = m0 + warpM * 32 + mt * 16 + g;
            int mB = mA + 8;
            if (mA < cnt) {
                float a0 = silu(accG[mt][nt][0] + bg0) * (accU[mt][nt][0] + bu0);
                float a1 = silu(accG[mt][nt][1] + bg1) * (accU[mt][nt][1] + bu1);
                *(uint32_t*)(g_acth + (size_t)(seg0 + mA) * INTER + n0 + ncol) = h2u(a0, a1);
            }
            if (mB < cnt) {
                float a2 = silu(accG[mt][nt][2] + bg0) * (accU[mt][nt][2] + bu0);
                float a3 = silu(accG[mt][nt][3] + bg1) * (accU[mt][nt][3] + bu1);
                *(uint32_t*)(g_acth + (size_t)(seg0 + mB) * INTER + n0 + ncol) = h2u(a2, a3);
            }
        }
    }
}

// ---------------- GEMM2: y = act @ W2^T + b2 -----------------------------------
__global__ __launch_bounds__(256, 2) void k_gemm2(const float* __restrict__ w2b) {
    extern __shared__ __align__(128) uint8_t smem[];
    float* sbias = (float*)(smem + 512);
    uint32_t sb = smem_u32(smem);
    uint32_t stage0 = sb + 1024;

    int e = blockIdx.z;
    int seg0 = g_offsets[e];
    int cnt  = g_offsets[e + 1] - seg0;
    int m0 = blockIdx.y * BM;
    if (m0 >= cnt) return;
    int n0 = blockIdx.x * BN;
    int tid = threadIdx.x, wid = tid >> 5, lid = tid & 31;
    int warpM = wid & 3, warpN = wid >> 2;

    if (tid < BN) sbias[tid] = w2b[(size_t)e * HIDDEN + n0 + tid];
    __syncthreads();

    const __half* wb = g_w2h + (size_t)e * HIDDEN * INTER + (size_t)n0 * INTER;
    const __half* aext = g_acth + (size_t)seg0 * INTER;
    int mclamp = cnt - 1;

    auto load_stage = [&](int s, int c) {
        uint32_t st = stage0 + s * STG2;
        int k0 = c * BK;
#pragma unroll
        for (int q = 0; q < 3; q++) {
            int ch = tid + q * 256;          // 0..767
            if (ch < 512) {
                int r = ch >> 2, c4 = ch & 3;
                int m = m0 + r; if (m > mclamp) m = mclamp;
                const __half* src = aext + (size_t)m * INTER + k0 + c4 * 8;
                CP16(st + r * PITCHB + c4 * 16, src);
            } else {
                int i = ch - 512, r = i >> 2, c4 = i & 3;
                const __half* src = wb + (size_t)r * INTER + k0 + c4 * 8;
                CP16(st + A_BYTES + r * PITCHB + c4 * 16, src);
            }
        }
        CP_COMMIT();
    };

    float acc[2][4][4];
#pragma unroll
    for (int i = 0; i < 2; i++)
#pragma unroll
        for (int j = 0; j < 4; j++)
#pragma unroll
            for (int q = 0; q < 4; q++) acc[i][j][q] = 0.f;

    load_stage(0, 0);
    load_stage(1, 1);
    load_stage(2, 2);

    int lrow = lid & 15;
    int lcolb = (lid & 16);

    for (int c = 0; c < NC; c++) {
        CP_WAIT2();
        __syncthreads();
        uint32_t st = stage0 + (c % 3) * STG2;
        uint32_t aBase = st + (warpM * 32 + lrow) * PITCHB + lcolb;
        uint32_t bBase = st + A_BYTES + (warpN * 32 + lrow) * PITCHB + lcolb;
#pragma unroll
        for (int kk = 0; kk < 2; kk++) {
            uint32_t koff = kk * 32;
            uint32_t a[2][4];
            ldsm4(a[0][0], a[0][1], a[0][2], a[0][3], aBase + koff);
            ldsm4(a[1][0], a[1][1], a[1][2], a[1][3], aBase + 16 * PITCHB + koff);
#pragma unroll
            for (int ntp = 0; ntp < 2; ntp++) {
                uint32_t b0, b1, b2, b3;
                ldsm4(b0, b1, b2, b3, bBase + ntp * 16 * PITCHB + koff);
#pragma unroll
                for (int mt = 0; mt < 2; mt++) {
                    mma16816(acc[mt][2 * ntp + 0], a[mt][0], a[mt][1], a[mt][2], a[mt][3], b0, b2);
                    mma16816(acc[mt][2 * ntp + 1], a[mt][0], a[mt][1], a[mt][2], a[mt][3], b1, b3);
                }
            }
        }
        __syncthreads();
        if (c + 3 < NC) load_stage(c % 3, c + 3);
        else CP_COMMIT();
    }

    int g = lid >> 2, t = lid & 3;
#pragma unroll
    for (int mt = 0; mt < 2; mt++) {
#pragma unroll
        for (int nt = 0; nt < 4; nt++) {
            int ncol = warpN * 32 + nt * 8 + 2 * t;
            float b0 = sbias[ncol], b1 = sbias[ncol + 1];
            int mA = m0 + warpM * 32 + mt * 16 + g;
            int mB = mA + 8;
            if (mA < cnt) {
                float2 o = make_float2(acc[mt][nt][0] + b0, acc[mt][nt][1] + b1);
                *(float2*)(g_y + (size_t)(seg0 + mA) * HIDDEN + n0 + ncol) = o;
            }
            if (mB < cnt) {
                float2 o = make_float2(acc[mt][nt][2] + b0, acc[mt][nt][3] + b1);
                *(float2*)(g_y + (size_t)(seg0 + mB) * HIDDEN + n0 + ncol) = o;
            }
        }
    }
}

// ---------------- final combine ------------------------------------------------
__global__ void k_combine(float* __restrict__ out) {
    int idx = blockIdx.x * blockDim.x + threadIdx.x;
    const int per_row = HIDDEN / 4;
    if (idx >= NUM_TOKENS * per_row) return;
    int t = idx / per_row;
    int hq = idx - t * per_row;
    int r1 = g_row_of[2 * t + 0];
    int r2 = g_row_of[2 * t + 1];
    float g1 = g_gate_of[2 * t + 0];
    float g2 = g_gate_of[2 * t + 1];
    float4 a = *((const float4*)(g_y + (size_t)r1 * HIDDEN) + hq);
    float4 b = *((const float4*)(g_y + (size_t)r2 * HIDDEN) + hq);
    float4 o;
    o.x = g1 * a.x + g2 * b.x;
    o.y = g1 * a.y + g2 * b.y;
    o.z = g1 * a.z + g2 * b.z;
    o.w = g1 * a.w + g2 * b.w;
    ((float4*)out)[idx] = o;
}

// ---------------- launch ---------------------------------------------------------
extern "C" void kernel_launch(void* const* d_in, const int* in_sizes, int n_in,
                              void* d_out, int out_size)
{
    const float* hs   = (const float*)d_in[0];
    const float* rl   = (const float*)d_in[1];
    const float* w13  = (const float*)d_in[2];
    const float* w2   = (const float*)d_in[3];
    const float* w13b = (const float*)d_in[4];
    const float* w2b  = (const float*)d_in[5];
    float* out = (float*)d_out;

    static bool attr_done = false;
    if (!attr_done) {
        cudaFuncSetAttribute(k_gemm1, cudaFuncAttributeMaxDynamicSharedMemorySize, G1_SMEM);
        cudaFuncSetAttribute(k_gemm2, cudaFuncAttributeMaxDynamicSharedMemorySize, G2_SMEM);
        attr_done = true;
    }

    k_init<<<1, 32>>>();
    k_route<<<(NUM_TOKENS + 255) / 256, 256>>>(rl);
    k_scan<<<1, 1>>>();
    k_scatter<<<(NUM_TOKENS + 255) / 256, 256>>>();

    __half* w13h_ptr = nullptr;  cudaGetSymbolAddress((void**)&w13h_ptr, g_w13h);
    __half* w2h_ptr  = nullptr;  cudaGetSymbolAddress((void**)&w2h_ptr,  g_w2h);
    __half* hsh_ptr  = nullptr;  cudaGetSymbolAddress((void**)&hsh_ptr,  g_hsh);

    {
        size_t n4 = (size_t)NUM_EXPERTS * N1 * HIDDEN / 4;
        k_cvt<<<(unsigned)((n4 + 255) / 256), 256>>>((const float4*)w13, (uint2*)w13h_ptr, n4);
    }
    {
        size_t n4 = (size_t)NUM_EXPERTS * HIDDEN * INTER / 4;
        k_cvt<<<(unsigned)((n4 + 255) / 256), 256>>>((const float4*)w2, (uint2*)w2h_ptr, n4);
    }
    {
        size_t n4 = (size_t)NUM_TOKENS * HIDDEN / 4;
        k_cvt<<<(unsigned)((n4 + 255) / 256), 256>>>((const float4*)hs, (uint2*)hsh_ptr, n4);
    }

    {
        dim3 grid(NT, MAXMT, NUM_EXPERTS);
        k_gemm1<<<grid, 256, G1_SMEM>>>(w13b);
    }
    {
        dim3 grid(NT, MAXMT, NUM_EXPERTS);
        k_gemm2<<<grid, 256, G2_SMEM>>>(w2b);
    }
    {
        int total = NUM_TOKENS * (HIDDEN / 4);
        k_combine<<<(total + 255) / 256, 256>>>(out);
    }
}

// round 5
// speedup vs baseline: 5.9126x; 1.1796x over previous
#include <cuda_runtime.h>
#include <cuda_fp16.h>
#include <cstdint>

#define NUM_TOKENS 4096
#define NUM_EXPERTS 16
#define HIDDEN 2880
#define INTER 2880
#define N1 (2 * INTER)          /* 5760 */
#define ROWS (NUM_TOKENS * 2)   /* 8192 expanded rows */

#define BM 128
#define BN1 64                  /* GEMM1 N tile (per gate/up) */
#define BN2 96                  /* GEMM2 N tile */
#define BK 64                   /* K chunk, halves */
#define NC (HIDDEN / BK)        /* 45 k-iterations */
#define NT1 (INTER / BN1)       /* 45 */
#define NT2 (HIDDEN / BN2)      /* 30 */
#define MAXTILES 80             /* sum ceil(cnt/128) <= 64 + 16 */

#define PITCHB 144              /* 64 halves = 128B + 16B pad */
#define A_BYTES (BM * PITCHB)   /* 18432 */
#define B1_BYTES (BN1 * PITCHB) /* 9216 */
#define B2_BYTES (BN2 * PITCHB) /* 13824 */
#define STG1 (A_BYTES + 2 * B1_BYTES)  /* 36864 */
#define STG2 (A_BYTES + B2_BYTES)      /* 32256 */
#define G1_SMEM (1024 + 2 * STG1)      /* 74752 */
#define G2_SMEM (1024 + 2 * STG2)      /* 65536 */

// ---------------- device scratch ----------------------------------------------
__device__ __align__(256) __half g_w13h[(size_t)NUM_EXPERTS * N1 * HIDDEN];
__device__ __align__(256) __half g_w2h[(size_t)NUM_EXPERTS * HIDDEN * INTER];
__device__ __align__(256) __half g_hsh[(size_t)NUM_TOKENS * HIDDEN];
__device__ __align__(256) __half g_acth[(size_t)ROWS * INTER];
__device__ __align__(256) float  g_y[(size_t)ROWS * HIDDEN];
__device__ int   g_rowmap[ROWS];
__device__ int   g_row_of[NUM_TOKENS * 2];
__device__ float g_gate_of[NUM_TOKENS * 2];
__device__ int   g_expert_of[NUM_TOKENS * 2];
__device__ int   g_counts[NUM_EXPERTS];
__device__ int   g_offsets[NUM_EXPERTS + 1];
__device__ int   g_cursor[NUM_EXPERTS];
__device__ int   g_ntiles;
__device__ int   g_tile_e[MAXTILES];
__device__ int   g_tile_m0[MAXTILES];

// ---------------- helpers ------------------------------------------------------
__device__ __forceinline__ uint32_t h2u(float a, float b) {
    __half2 h = __floats2half2_rn(a, b);
    return *reinterpret_cast<uint32_t*>(&h);
}
__device__ __forceinline__ uint32_t smem_u32(const void* p) {
    uint32_t a;
    asm("{ .reg .u64 t; cvta.to.shared.u64 t, %1; cvt.u32.u64 %0, t; }"
        : "=r"(a) : "l"(p));
    return a;
}
#define CP16(dst, src) \
    asm volatile("cp.async.cg.shared.global [%0], [%1], 16;" :: "r"(dst), "l"(src))
#define CP_COMMIT() asm volatile("cp.async.commit_group;" ::: "memory")
#define CP_WAIT1()  asm volatile("cp.async.wait_group 1;" ::: "memory")

__device__ __forceinline__ void ldsm4(uint32_t& r0, uint32_t& r1, uint32_t& r2,
                                      uint32_t& r3, uint32_t addr) {
    asm volatile("ldmatrix.sync.aligned.m8n8.x4.shared.b16 {%0,%1,%2,%3}, [%4];"
                 : "=r"(r0), "=r"(r1), "=r"(r2), "=r"(r3) : "r"(addr));
}
__device__ __forceinline__ void mma16816(float* c, uint32_t a0, uint32_t a1,
                                         uint32_t a2, uint32_t a3,
                                         uint32_t b0, uint32_t b1) {
    asm volatile(
        "mma.sync.aligned.m16n8k16.row.col.f32.f16.f16.f32 "
        "{%0,%1,%2,%3}, {%4,%5,%6,%7}, {%8,%9}, {%0,%1,%2,%3};"
        : "+f"(c[0]), "+f"(c[1]), "+f"(c[2]), "+f"(c[3])
        : "r"(a0), "r"(a1), "r"(a2), "r"(a3), "r"(b0), "r"(b1));
}
__device__ __forceinline__ float silu(float x) {
    return x / (1.0f + expf(-x));
}

// ---------------- routing ----------------------------------------------------
__global__ void k_init() {
    int i = threadIdx.x;
    if (i < NUM_EXPERTS) { g_counts[i] = 0; g_cursor[i] = 0; }
}
__global__ void k_route(const float* __restrict__ logits) {
    int t = blockIdx.x * blockDim.x + threadIdx.x;
    if (t >= NUM_TOKENS) return;
    const float* l = logits + (size_t)t * NUM_EXPERTS;
    float v[NUM_EXPERTS];
#pragma unroll
    for (int e = 0; e < NUM_EXPERTS; e++) v[e] = l[e];
    int i1 = 0; float v1 = v[0];
#pragma unroll
    for (int e = 1; e < NUM_EXPERTS; e++) if (v[e] > v1) { v1 = v[e]; i1 = e; }
    int i2 = -1; float v2 = -1e30f;
#pragma unroll
    for (int e = 0; e < NUM_EXPERTS; e++)
        if (e != i1 && v[e] > v2) { v2 = v[e]; i2 = e; }
    float g1 = 1.0f / (1.0f + expf(v2 - v1));
    g_expert_of[2 * t + 0] = i1;  g_gate_of[2 * t + 0] = g1;
    g_expert_of[2 * t + 1] = i2;  g_gate_of[2 * t + 1] = 1.0f - g1;
    atomicAdd(&g_counts[i1], 1);
    atomicAdd(&g_counts[i2], 1);
}
__global__ void k_scan() {
    if (threadIdx.x == 0) {
        int acc = 0;
        for (int e = 0; e < NUM_EXPERTS; e++) { g_offsets[e] = acc; acc += g_counts[e]; }
        g_offsets[NUM_EXPERTS] = acc;
        int nt = 0;
        for (int e = 0; e < NUM_EXPERTS; e++) {
            int cnt = g_counts[e];
            for (int m0 = 0; m0 < cnt; m0 += BM) {
                g_tile_e[nt] = e;
                g_tile_m0[nt] = m0;
                nt++;
            }
        }
        g_ntiles = nt;
    }
}
__global__ void k_scatter() {
    int t = blockIdx.x * blockDim.x + threadIdx.x;
    if (t >= NUM_TOKENS) return;
#pragma unroll
    for (int k = 0; k < 2; k++) {
        int e = g_expert_of[2 * t + k];
        int pos = g_offsets[e] + atomicAdd(&g_cursor[e], 1);
        g_rowmap[pos] = t;
        g_row_of[2 * t + k] = pos;
    }
}

// ---------------- fp32 -> fp16 -------------------------------------------------
__global__ void k_cvt(const float4* __restrict__ src, uint2* __restrict__ dst,
                      size_t n4) {
    size_t i = (size_t)blockIdx.x * blockDim.x + threadIdx.x;
    if (i >= n4) return;
    float4 v = src[i];
    uint2 o;
    o.x = h2u(v.x, v.y);
    o.y = h2u(v.z, v.w);
    dst[i] = o;
}

// ---------------- GEMM1: act = silu(X@Wg^T+bg) * (X@Wu^T+bu) -------------------
// smem: [0:512) stok int[128] | [512:1024) sbias float[128] | [1024+): 2 stages
__global__ __launch_bounds__(256, 2) void k_gemm1(const float* __restrict__ w13b) {
    extern __shared__ __align__(128) uint8_t smem[];
    int* stok = (int*)smem;
    float* sbias = (float*)(smem + 512);
    uint32_t sb = smem_u32(smem);
    uint32_t stage0 = sb + 1024;

    int ty = blockIdx.y;
    if (ty >= g_ntiles) return;
    int e = g_tile_e[ty];
    int m0 = g_tile_m0[ty];
    int seg0 = g_offsets[e];
    int cnt  = g_offsets[e + 1] - seg0;
    int n0 = blockIdx.x * BN1;
    int tid = threadIdx.x, wid = tid >> 5, lid = tid & 31;
    int warpM = wid & 3, warpN = wid >> 2;

    if (tid < BM) {
        int m = m0 + tid;
        stok[tid] = g_rowmap[seg0 + (m < cnt ? m : cnt - 1)];
    }
    if (tid >= 128 && tid < 192)
        sbias[tid - 128] = w13b[(size_t)e * N1 + n0 + (tid - 128)];
    else if (tid >= 192)
        sbias[tid - 192 + 64] = w13b[(size_t)e * N1 + INTER + n0 + (tid - 192)];
    __syncthreads();

    const __half* wg = g_w13h + (size_t)e * N1 * HIDDEN + (size_t)n0 * HIDDEN;
    const __half* wu = g_w13h + (size_t)e * N1 * HIDDEN + (size_t)(INTER + n0) * HIDDEN;

    auto load_stage = [&](int s, int c) {
        uint32_t st = stage0 + s * STG1;
        int k0 = c * BK;
#pragma unroll
        for (int q = 0; q < 8; q++) {
            int ch = tid + q * 256;          // 0..2047
            if (ch < 1024) {                 // A: 128 rows x 8 chunks of 16B
                int r = ch >> 3, c8 = ch & 7;
                const __half* src = g_hsh + (size_t)stok[r] * HIDDEN + k0 + c8 * 8;
                CP16(st + r * PITCHB + c8 * 16, src);
            } else if (ch < 1536) {          // Bg: 64 rows x 8
                int i = ch - 1024, r = i >> 3, c8 = i & 7;
                const __half* src = wg + (size_t)r * HIDDEN + k0 + c8 * 8;
                CP16(st + A_BYTES + r * PITCHB + c8 * 16, src);
            } else {                         // Bu
                int i = ch - 1536, r = i >> 3, c8 = i & 7;
                const __half* src = wu + (size_t)r * HIDDEN + k0 + c8 * 8;
                CP16(st + A_BYTES + B1_BYTES + r * PITCHB + c8 * 16, src);
            }
        }
        CP_COMMIT();
    };

    float accG[2][4][4], accU[2][4][4];
#pragma unroll
    for (int i = 0; i < 2; i++)
#pragma unroll
        for (int j = 0; j < 4; j++)
#pragma unroll
            for (int q = 0; q < 4; q++) { accG[i][j][q] = 0.f; accU[i][j][q] = 0.f; }

    load_stage(0, 0);
    load_stage(1, 1);

    int lrow = lid & 15;
    int lcolb = (lid & 16);                  // 0 or 16 bytes

    for (int c = 0; c < NC; c++) {
        CP_WAIT1();
        __syncthreads();
        uint32_t st = stage0 + (c & 1) * STG1;
        uint32_t aBase = st + (warpM * 32 + lrow) * PITCHB + lcolb;
        uint32_t gBase = st + A_BYTES + (warpN * 32 + lrow) * PITCHB + lcolb;
        uint32_t uBase = gBase + B1_BYTES;
#pragma unroll
        for (int kk = 0; kk < 4; kk++) {     // four k16 steps
            uint32_t koff = kk * 32;
            uint32_t a[2][4];
            ldsm4(a[0][0], a[0][1], a[0][2], a[0][3], aBase + koff);
            ldsm4(a[1][0], a[1][1], a[1][2], a[1][3], aBase + 16 * PITCHB + koff);
#pragma unroll
            for (int ntp = 0; ntp < 2; ntp++) {
                uint32_t b0, b1, b2, b3;
                ldsm4(b0, b1, b2, b3, gBase + ntp * 16 * PITCHB + koff);
#pragma unroll
                for (int mt = 0; mt < 2; mt++) {
                    mma16816(accG[mt][2 * ntp + 0], a[mt][0], a[mt][1], a[mt][2], a[mt][3], b0, b2);
                    mma16816(accG[mt][2 * ntp + 1], a[mt][0], a[mt][1], a[mt][2], a[mt][3], b1, b3);
                }
                ldsm4(b0, b1, b2, b3, uBase + ntp * 16 * PITCHB + koff);
#pragma unroll
                for (int mt = 0; mt < 2; mt++) {
                    mma16816(accU[mt][2 * ntp + 0], a[mt][0], a[mt][1], a[mt][2], a[mt][3], b0, b2);
                    mma16816(accU[mt][2 * ntp + 1], a[mt][0], a[mt][1], a[mt][2], a[mt][3], b1, b3);
                }
            }
        }
        __syncthreads();
        if (c + 2 < NC) load_stage(c & 1, c + 2);
        else CP_COMMIT();
    }

    int g = lid >> 2, t = lid & 3;
#pragma unroll
    for (int mt = 0; mt < 2; mt++) {
#pragma unroll
        for (int nt = 0; nt < 4; nt++) {
            int ncol = warpN * 32 + nt * 8 + 2 * t;
            float bg0 = sbias[ncol], bg1 = sbias[ncol + 1];
            float bu0 = sbias[64 + ncol], bu1 = sbias[64 + ncol + 1];
            int mA = m0 + warpM * 32 + mt * 16 + g;
            int mB = mA + 8;
            if (mA < cnt) {
                float a0 = silu(accG[mt][nt][0] + bg0) * (accU[mt][nt][0] + bu0);
                float a1 = silu(accG[mt][nt][1] + bg1) * (accU[mt][nt][1] + bu1);
                *(uint32_t*)(g_acth + (size_t)(seg0 + mA) * INTER + n0 + ncol) = h2u(a0, a1);
            }
            if (mB < cnt) {
                float a2 = silu(accG[mt][nt][2] + bg0) * (accU[mt][nt][2] + bu0);
                float a3 = silu(accG[mt][nt][3] + bg1) * (accU[mt][nt][3] + bu1);
                *(uint32_t*)(g_acth + (size_t)(seg0 + mB) * INTER + n0 + ncol) = h2u(a2, a3);
            }
        }
    }
}

// ---------------- GEMM2: y = act @ W2^T + b2 (BN=96) ---------------------------
__global__ __launch_bounds__(256, 2) void k_gemm2(const float* __restrict__ w2b) {
    extern __shared__ __align__(128) uint8_t smem[];
    float* sbias = (float*)(smem + 512);
    uint32_t sb = smem_u32(smem);
    uint32_t stage0 = sb + 1024;

    int ty = blockIdx.y;
    if (ty >= g_ntiles) return;
    int e = g_tile_e[ty];
    int m0 = g_tile_m0[ty];
    int seg0 = g_offsets[e];
    int cnt  = g_offsets[e + 1] - seg0;
    int n0 = blockIdx.x * BN2;
    int tid = threadIdx.x, wid = tid >> 5, lid = tid & 31;
    int warpM = wid & 3, warpN = wid >> 2;

    if (tid < BN2) sbias[tid] = w2b[(size_t)e * HIDDEN + n0 + tid];
    __syncthreads();

    const __half* wb = g_w2h + (size_t)e * HIDDEN * INTER + (size_t)n0 * INTER;
    const __half* aext = g_acth + (size_t)seg0 * INTER;
    int mclamp = cnt - 1;

    auto load_stage = [&](int s, int c) {
        uint32_t st = stage0 + s * STG2;
        int k0 = c * BK;
#pragma unroll
        for (int q = 0; q < 7; q++) {
            int ch = tid + q * 256;          // 0..1791
            if (ch < 1024) {                 // A: 128 rows x 8
                int r = ch >> 3, c8 = ch & 7;
                int m = m0 + r; if (m > mclamp) m = mclamp;
                const __half* src = aext + (size_t)m * INTER + k0 + c8 * 8;
                CP16(st + r * PITCHB + c8 * 16, src);
            } else {                         // B: 96 rows x 8
                int i = ch - 1024, r = i >> 3, c8 = i & 7;
                const __half* src = wb + (size_t)r * INTER + k0 + c8 * 8;
                CP16(st + A_BYTES + r * PITCHB + c8 * 16, src);
            }
        }
        CP_COMMIT();
    };

    float acc[2][6][4];
#pragma unroll
    for (int i = 0; i < 2; i++)
#pragma unroll
        for (int j = 0; j < 6; j++)
#pragma unroll
            for (int q = 0; q < 4; q++) acc[i][j][q] = 0.f;

    load_stage(0, 0);
    load_stage(1, 1);

    int lrow = lid & 15;
    int lcolb = (lid & 16);

    for (int c = 0; c < NC; c++) {
        CP_WAIT1();
        __syncthreads();
        uint32_t st = stage0 + (c & 1) * STG2;
        uint32_t aBase = st + (warpM * 32 + lrow) * PITCHB + lcolb;
        uint32_t bBase = st + A_BYTES + (warpN * 48 + lrow) * PITCHB + lcolb;
#pragma unroll
        for (int kk = 0; kk < 4; kk++) {
            uint32_t koff = kk * 32;
            uint32_t a[2][4];
            ldsm4(a[0][0], a[0][1], a[0][2], a[0][3], aBase + koff);
            ldsm4(a[1][0], a[1][1], a[1][2], a[1][3], aBase + 16 * PITCHB + koff);
#pragma unroll
            for (int ntp = 0; ntp < 3; ntp++) {
                uint32_t b0, b1, b2, b3;
                ldsm4(b0, b1, b2, b3, bBase + ntp * 16 * PITCHB + koff);
#pragma unroll
                for (int mt = 0; mt < 2; mt++) {
                    mma16816(acc[mt][2 * ntp + 0], a[mt][0], a[mt][1], a[mt][2], a[mt][3], b0, b2);
                    mma16816(acc[mt][2 * ntp + 1], a[mt][0], a[mt][1], a[mt][2], a[mt][3], b1, b3);
                }
            }
        }
        __syncthreads();
        if (c + 2 < NC) load_stage(c & 1, c + 2);
        else CP_COMMIT();
    }

    int g = lid >> 2, t = lid & 3;
#pragma unroll
    for (int mt = 0; mt < 2; mt++) {
#pragma unroll
        for (int nt = 0; nt < 6; nt++) {
            int ncol = warpN * 48 + nt * 8 + 2 * t;
            float b0 = sbias[ncol], b1 = sbias[ncol + 1];
            int mA = m0 + warpM * 32 + mt * 16 + g;
            int mB = mA + 8;
            if (mA < cnt) {
                float2 o = make_float2(acc[mt][nt][0] + b0, acc[mt][nt][1] + b1);
                *(float2*)(g_y + (size_t)(seg0 + mA) * HIDDEN + n0 + ncol) = o;
            }
            if (mB < cnt) {
                float2 o = make_float2(acc[mt][nt][2] + b0, acc[mt][nt][3] + b1);
                *(float2*)(g_y + (size_t)(seg0 + mB) * HIDDEN + n0 + ncol) = o;
            }
        }
    }
}

// ---------------- final combine ------------------------------------------------
__global__ void k_combine(float* __restrict__ out) {
    int idx = blockIdx.x * blockDim.x + threadIdx.x;
    const int per_row = HIDDEN / 4;
    if (idx >= NUM_TOKENS * per_row) return;
    int t = idx / per_row;
    int hq = idx - t * per_row;
    int r1 = g_row_of[2 * t + 0];
    int r2 = g_row_of[2 * t + 1];
    float g1 = g_gate_of[2 * t + 0];
    float g2 = g_gate_of[2 * t + 1];
    float4 a = *((const float4*)(g_y + (size_t)r1 * HIDDEN) + hq);
    float4 b = *((const float4*)(g_y + (size_t)r2 * HIDDEN) + hq);
    float4 o;
    o.x = g1 * a.x + g2 * b.x;
    o.y = g1 * a.y + g2 * b.y;
    o.z = g1 * a.z + g2 * b.z;
    o.w = g1 * a.w + g2 * b.w;
    ((float4*)out)[idx] = o;
}

// ---------------- launch ---------------------------------------------------------
extern "C" void kernel_launch(void* const* d_in, const int* in_sizes, int n_in,
                              void* d_out, int out_size)
{
    const float* hs   = (const float*)d_in[0];
    const float* rl   = (const float*)d_in[1];
    const float* w13  = (const float*)d_in[2];
    const float* w2   = (const float*)d_in[3];
    const float* w13b = (const float*)d_in[4];
    const float* w2b  = (const float*)d_in[5];
    float* out = (float*)d_out;

    static bool attr_done = false;
    if (!attr_done) {
        cudaFuncSetAttribute(k_gemm1, cudaFuncAttributeMaxDynamicSharedMemorySize, G1_SMEM);
        cudaFuncSetAttribute(k_gemm2, cudaFuncAttributeMaxDynamicSharedMemorySize, G2_SMEM);
        attr_done = true;
    }

    k_init<<<1, 32>>>();
    k_route<<<(NUM_TOKENS + 255) / 256, 256>>>(rl);
    k_scan<<<1, 1>>>();
    k_scatter<<<(NUM_TOKENS + 255) / 256, 256>>>();

    __half* w13h_ptr = nullptr;  cudaGetSymbolAddress((void**)&w13h_ptr, g_w13h);
    __half* w2h_ptr  = nullptr;  cudaGetSymbolAddress((void**)&w2h_ptr,  g_w2h);
    __half* hsh_ptr  = nullptr;  cudaGetSymbolAddress((void**)&hsh_ptr,  g_hsh);

    {
        size_t n4 = (size_t)NUM_EXPERTS * N1 * HIDDEN / 4;
        k_cvt<<<(unsigned)((n4 + 255) / 256), 256>>>((const float4*)w13, (uint2*)w13h_ptr, n4);
    }
    {
        size_t n4 = (size_t)NUM_EXPERTS * HIDDEN * INTER / 4;
        k_cvt<<<(unsigned)((n4 + 255) / 256), 256>>>((const float4*)w2, (uint2*)w2h_ptr, n4);
    }
    {
        size_t n4 = (size_t)NUM_TOKENS * HIDDEN / 4;
        k_cvt<<<(unsigned)((n4 + 255) / 256), 256>>>((const float4*)hs, (uint2*)hsh_ptr, n4);
    }

    {
        dim3 grid(NT1, MAXTILES);
        k_gemm1<<<grid, 256, G1_SMEM>>>(w13b);
    }
    {
        dim3 grid(NT2, MAXTILES);
        k_gemm2<<<grid, 256, G2_SMEM>>>(w2b);
    }
    {
        int total = NUM_TOKENS * (HIDDEN / 4);
        k_combine<<<(total + 255) / 256, 256>>>(out);
    }
}

// round 7
// speedup vs baseline: 5.9146x; 1.0003x over previous
#include <cuda_runtime.h>
#include <cuda_fp16.h>
#include <cstdint>

#define NUM_TOKENS 4096
#define NUM_EXPERTS 16
#define HIDDEN 2880
#define INTER 2880
#define N1 (2 * INTER)          /* 5760 */
#define ROWS (NUM_TOKENS * 2)   /* 8192 expanded rows */

#define BM 128
#define BN1 64                  /* GEMM1 N tile (per gate/up) */
#define BN2 96                  /* GEMM2 N tile */
#define BK 64                   /* K chunk, halves */
#define NC (HIDDEN / BK)        /* 45 k-iterations */
#define NT1 (INTER / BN1)       /* 45 */
#define NT2 (HIDDEN / BN2)      /* 30 */
#define MAXTILES 80             /* sum ceil(cnt/128) <= 64 + 16 */

#define PITCHB 144              /* 64 halves = 128B + 16B pad */
#define A_BYTES (BM * PITCHB)   /* 18432 */
#define B1_BYTES (BN1 * PITCHB) /* 9216 */
#define B2_BYTES (BN2 * PITCHB) /* 13824 */
#define STG1 (A_BYTES + 2 * B1_BYTES)  /* 36864 */
#define STG2 (A_BYTES + B2_BYTES)      /* 32256 */
#define G1_SMEM (1024 + 3 * STG1)      /* 111616 */
#define G2_SMEM (1024 + 3 * STG2)      /* 97792 */

// ---------------- device scratch ----------------------------------------------
__device__ __align__(256) __half g_w13h[(size_t)NUM_EXPERTS * N1 * HIDDEN];
__device__ __align__(256) __half g_w2h[(size_t)NUM_EXPERTS * HIDDEN * INTER];
__device__ __align__(256) __half g_hsh[(size_t)NUM_TOKENS * HIDDEN];
__device__ __align__(256) __half g_acth[(size_t)ROWS * INTER];
__device__ __align__(256) float  g_y[(size_t)ROWS * HIDDEN];
__device__ int   g_rowmap[ROWS];
__device__ int   g_row_of[NUM_TOKENS * 2];
__device__ float g_gate_of[NUM_TOKENS * 2];
__device__ int   g_expert_of[NUM_TOKENS * 2];
__device__ int   g_counts[NUM_EXPERTS];
__device__ int   g_offsets[NUM_EXPERTS + 1];
__device__ int   g_cursor[NUM_EXPERTS];
__device__ int   g_ntiles;
__device__ int   g_tile_e[MAXTILES];
__device__ int   g_tile_m0[MAXTILES];

// ---------------- helpers ------------------------------------------------------
__device__ __forceinline__ uint32_t h2u(float a, float b) {
    __half2 h = __floats2half2_rn(a, b);
    return *reinterpret_cast<uint32_t*>(&h);
}
__device__ __forceinline__ uint32_t smem_u32(const void* p) {
    uint32_t a;
    asm("{ .reg .u64 t; cvta.to.shared.u64 t, %1; cvt.u32.u64 %0, t; }"
        : "=r"(a) : "l"(p));
    return a;
}
#define CP16(dst, src) \
    asm volatile("cp.async.cg.shared.global [%0], [%1], 16;" :: "r"(dst), "l"(src))
#define CP_COMMIT() asm volatile("cp.async.commit_group;" ::: "memory")
#define CP_WAIT1()  asm volatile("cp.async.wait_group 1;" ::: "memory")

__device__ __forceinline__ void ldsm4(uint32_t& r0, uint32_t& r1, uint32_t& r2,
                                      uint32_t& r3, uint32_t addr) {
    asm volatile("ldmatrix.sync.aligned.m8n8.x4.shared.b16 {%0,%1,%2,%3}, [%4];"
                 : "=r"(r0), "=r"(r1), "=r"(r2), "=r"(r3) : "r"(addr));
}
__device__ __forceinline__ void mma16816(float* c, uint32_t a0, uint32_t a1,
                                         uint32_t a2, uint32_t a3,
                                         uint32_t b0, uint32_t b1) {
    asm volatile(
        "mma.sync.aligned.m16n8k16.row.col.f32.f16.f16.f32 "
        "{%0,%1,%2,%3}, {%4,%5,%6,%7}, {%8,%9}, {%0,%1,%2,%3};"
        : "+f"(c[0]), "+f"(c[1]), "+f"(c[2]), "+f"(c[3])
        : "r"(a0), "r"(a1), "r"(a2), "r"(a3), "r"(b0), "r"(b1));
}
__device__ __forceinline__ float silu(float x) {
    return x / (1.0f + __expf(-x));
}

// ---------------- routing ----------------------------------------------------
__global__ void k_init() {
    int i = threadIdx.x;
    if (i < NUM_EXPERTS) { g_counts[i] = 0; g_cursor[i] = 0; }
}
__global__ void k_route(const float* __restrict__ logits) {
    int t = blockIdx.x * blockDim.x + threadIdx.x;
    if (t >= NUM_TOKENS) return;
    const float* l = logits + (size_t)t * NUM_EXPERTS;
    float v[NUM_EXPERTS];
#pragma unroll
    for (int e = 0; e < NUM_EXPERTS; e++) v[e] = l[e];
    int i1 = 0; float v1 = v[0];
#pragma unroll
    for (int e = 1; e < NUM_EXPERTS; e++) if (v[e] > v1) { v1 = v[e]; i1 = e; }
    int i2 = -1; float v2 = -1e30f;
#pragma unroll
    for (int e = 0; e < NUM_EXPERTS; e++)
        if (e != i1 && v[e] > v2) { v2 = v[e]; i2 = e; }
    float g1 = 1.0f / (1.0f + expf(v2 - v1));
    g_expert_of[2 * t + 0] = i1;  g_gate_of[2 * t + 0] = g1;
    g_expert_of[2 * t + 1] = i2;  g_gate_of[2 * t + 1] = 1.0f - g1;
    atomicAdd(&g_counts[i1], 1);
    atomicAdd(&g_counts[i2], 1);
}
__global__ void k_scan() {
    if (threadIdx.x == 0) {
        int acc = 0;
        for (int e = 0; e < NUM_EXPERTS; e++) { g_offsets[e] = acc; acc += g_counts[e]; }
        g_offsets[NUM_EXPERTS] = acc;
        int nt = 0;
        for (int e = 0; e < NUM_EXPERTS; e++) {
            int cnt = g_counts[e];
            for (int m0 = 0; m0 < cnt; m0 += BM) {
                g_tile_e[nt] = e;
                g_tile_m0[nt] = m0;
                nt++;
            }
        }
        g_ntiles = nt;
    }
}
__global__ void k_scatter() {
    int t = blockIdx.x * blockDim.x + threadIdx.x;
    if (t >= NUM_TOKENS) return;
#pragma unroll
    for (int k = 0; k < 2; k++) {
        int e = g_expert_of[2 * t + k];
        int pos = g_offsets[e] + atomicAdd(&g_cursor[e], 1);
        g_rowmap[pos] = t;
        g_row_of[2 * t + k] = pos;
    }
}

// ---------------- fp32 -> fp16 -------------------------------------------------
__global__ void k_cvt(const float4* __restrict__ src, uint2* __restrict__ dst,
                      size_t n4) {
    size_t i = (size_t)blockIdx.x * blockDim.x + threadIdx.x;
    if (i >= n4) return;
    float4 v = src[i];
    uint2 o;
    o.x = h2u(v.x, v.y);
    o.y = h2u(v.z, v.w);
    dst[i] = o;
}

// ---------------- GEMM1: act = silu(X@Wg^T+bg) * (X@Wu^T+bu) -------------------
// smem: [0:512) stok int[128] | [512:1024) sbias float[128] | [1024+): 3 stages
__global__ __launch_bounds__(256, 2) void k_gemm1(const float* __restrict__ w13b) {
    extern __shared__ __align__(128) uint8_t smem[];
    int* stok = (int*)smem;
    float* sbias = (float*)(smem + 512);
    uint32_t sb = smem_u32(smem);
    uint32_t stage0 = sb + 1024;

    int ty = blockIdx.y;
    if (ty >= g_ntiles) return;
    int e = g_tile_e[ty];
    int m0 = g_tile_m0[ty];
    int seg0 = g_offsets[e];
    int cnt  = g_offsets[e + 1] - seg0;
    int n0 = blockIdx.x * BN1;
    int tid = threadIdx.x, wid = tid >> 5, lid = tid & 31;
    int warpM = wid & 3, warpN = wid >> 2;

    if (tid < BM) {
        int m = m0 + tid;
        stok[tid] = g_rowmap[seg0 + (m < cnt ? m : cnt - 1)];
    }
    if (tid >= 128 && tid < 192)
        sbias[tid - 128] = w13b[(size_t)e * N1 + n0 + (tid - 128)];
    else if (tid >= 192)
        sbias[tid - 192 + 64] = w13b[(size_t)e * N1 + INTER + n0 + (tid - 192)];
    __syncthreads();

    const __half* wg = g_w13h + (size_t)e * N1 * HIDDEN + (size_t)n0 * HIDDEN;
    const __half* wu = g_w13h + (size_t)e * N1 * HIDDEN + (size_t)(INTER + n0) * HIDDEN;

    auto load_stage = [&](int s, int c) {
        uint32_t st = stage0 + s * STG1;
        int k0 = c * BK;
#pragma unroll
        for (int q = 0; q < 8; q++) {
            int ch = tid + q * 256;          // 0..2047
            if (ch < 1024) {                 // A: 128 rows x 8 chunks of 16B
                int r = ch >> 3, c8 = ch & 7;
                const __half* src = g_hsh + (size_t)stok[r] * HIDDEN + k0 + c8 * 8;
                CP16(st + r * PITCHB + c8 * 16, src);
            } else if (ch < 1536) {          // Bg: 64 rows x 8
                int i = ch - 1024, r = i >> 3, c8 = i & 7;
                const __half* src = wg + (size_t)r * HIDDEN + k0 + c8 * 8;
                CP16(st + A_BYTES + r * PITCHB + c8 * 16, src);
            } else {                         // Bu
                int i = ch - 1536, r = i >> 3, c8 = i & 7;
                const __half* src = wu + (size_t)r * HIDDEN + k0 + c8 * 8;
                CP16(st + A_BYTES + B1_BYTES + r * PITCHB + c8 * 16, src);
            }
        }
        CP_COMMIT();
    };

    float accG[2][4][4], accU[2][4][4];
#pragma unroll
    for (int i = 0; i < 2; i++)
#pragma unroll
        for (int j = 0; j < 4; j++)
#pragma unroll
            for (int q = 0; q < 4; q++) { accG[i][j][q] = 0.f; accU[i][j][q] = 0.f; }

    load_stage(0, 0);
    load_stage(1, 1);

    int lrow = lid & 15;
    int lcolb = (lid & 16);                  // 0 or 16 bytes

    for (int c = 0; c < NC; c++) {
        CP_WAIT1();
        __syncthreads();
        if (c + 2 < NC) load_stage((c + 2) % 3, c + 2);   // into stage (c-1)%3
        else CP_COMMIT();                    // keep group ledger advancing (tail)
        uint32_t st = stage0 + (c % 3) * STG1;
        uint32_t aBase = st + (warpM * 32 + lrow) * PITCHB + lcolb;
        uint32_t gBase = st + A_BYTES + (warpN * 32 + lrow) * PITCHB + lcolb;
        uint32_t uBase = gBase + B1_BYTES;
#pragma unroll
        for (int kk = 0; kk < 4; kk++) {     // four k16 steps
            uint32_t koff = kk * 32;
            uint32_t a[2][4];
            ldsm4(a[0][0], a[0][1], a[0][2], a[0][3], aBase + koff);
            ldsm4(a[1][0], a[1][1], a[1][2], a[1][3], aBase + 16 * PITCHB + koff);
#pragma unroll
            for (int ntp = 0; ntp < 2; ntp++) {
                uint32_t b0, b1, b2, b3;
                ldsm4(b0, b1, b2, b3, gBase + ntp * 16 * PITCHB + koff);
#pragma unroll
                for (int mt = 0; mt < 2; mt++) {
                    mma16816(accG[mt][2 * ntp + 0], a[mt][0], a[mt][1], a[mt][2], a[mt][3], b0, b2);
                    mma16816(accG[mt][2 * ntp + 1], a[mt][0], a[mt][1], a[mt][2], a[mt][3], b1, b3);
                }
                ldsm4(b0, b1, b2, b3, uBase + ntp * 16 * PITCHB + koff);
#pragma unroll
                for (int mt = 0; mt < 2; mt++) {
                    mma16816(accU[mt][2 * ntp + 0], a[mt][0], a[mt][1], a[mt][2], a[mt][3], b0, b2);
                    mma16816(accU[mt][2 * ntp + 1], a[mt][0], a[mt][1], a[mt][2], a[mt][3], b1, b3);
                }
            }
        }
    }

    int g = lid >> 2, t = lid & 3;
#pragma unroll
    for (int mt = 0; mt < 2; mt++) {
#pragma unroll
        for (int nt = 0; nt < 4; nt++) {
            int ncol = warpN * 32 + nt * 8 + 2 * t;
            float bg0 = sbias[ncol], bg1 = sbias[ncol + 1];
            float bu0 = sbias[64 + ncol], bu1 = sbias[64 + ncol + 1];
            int mA = m0 + warpM * 32 + mt * 16 + g;
            int mB = mA + 8;
            if (mA < cnt) {
                float a0 = silu(accG[mt][nt][0] + bg0) * (accU[mt][nt][0] + bu0);
                float a1 = silu(accG[mt][nt][1] + bg1) * (accU[mt][nt][1] + bu1);
                *(uint32_t*)(g_acth + (size_t)(seg0 + mA) * INTER + n0 + ncol) = h2u(a0, a1);
            }
            if (mB < cnt) {
                float a2 = silu(accG[mt][nt][2] + bg0) * (accU[mt][nt][2] + bu0);
                float a3 = silu(accG[mt][nt][3] + bg1) * (accU[mt][nt][3] + bu1);
                *(uint32_t*)(g_acth + (size_t)(seg0 + mB) * INTER + n0 + ncol) = h2u(a2, a3);
            }
        }
    }
}

// ---------------- GEMM2: y = act @ W2^T + b2 (BN=96) ---------------------------
__global__ __launch_bounds__(256, 2) void k_gemm2(const float* __restrict__ w2b) {
    extern __shared__ __align__(128) uint8_t smem[];
    float* sbias = (float*)(smem + 512);
    uint32_t sb = smem_u32(smem);
    uint32_t stage0 = sb + 1024;

    int ty = blockIdx.y;
    if (ty >= g_ntiles) return;
    int e = g_tile_e[ty];
    int m0 = g_tile_m0[ty];
    int seg0 = g_offsets[e];
    int cnt  = g_offsets[e + 1] - seg0;
    int n0 = blockIdx.x * BN2;
    int tid = threadIdx.x, wid = tid >> 5, lid = tid & 31;
    int warpM = wid & 3, warpN = wid >> 2;

    if (tid < BN2) sbias[tid] = w2b[(size_t)e * HIDDEN + n0 + tid];
    __syncthreads();

    const __half* wb = g_w2h + (size_t)e * HIDDEN * INTER + (size_t)n0 * INTER;
    const __half* aext = g_acth + (size_t)seg0 * INTER;
    int mclamp = cnt - 1;

    auto load_stage = [&](int s, int c) {
        uint32_t st = stage0 + s * STG2;
        int k0 = c * BK;
#pragma unroll
        for (int q = 0; q < 7; q++) {
            int ch = tid + q * 256;          // 0..1791
            if (ch < 1024) {                 // A: 128 rows x 8
                int r = ch >> 3, c8 = ch & 7;
                int m = m0 + r; if (m > mclamp) m = mclamp;
                const __half* src = aext + (size_t)m * INTER + k0 + c8 * 8;
                CP16(st + r * PITCHB + c8 * 16, src);
            } else {                         // B: 96 rows x 8
                int i = ch - 1024, r = i >> 3, c8 = i & 7;
                const __half* src = wb + (size_t)r * INTER + k0 + c8 * 8;
                CP16(st + A_BYTES + r * PITCHB + c8 * 16, src);
            }
        }
        CP_COMMIT();
    };

    float acc[2][6][4];
#pragma unroll
    for (int i = 0; i < 2; i++)
#pragma unroll
        for (int j = 0; j < 6; j++)
#pragma unroll
            for (int q = 0; q < 4; q++) acc[i][j][q] = 0.f;

    load_stage(0, 0);
    load_stage(1, 1);

    int lrow = lid & 15;
    int lcolb = (lid & 16);

    for (int c = 0; c < NC; c++) {
        CP_WAIT1();
        __syncthreads();
        if (c + 2 < NC) load_stage((c + 2) % 3, c + 2);
        else CP_COMMIT();                    // keep group ledger advancing (tail)
        uint32_t st = stage0 + (c % 3) * STG2;
        uint32_t aBase = st + (warpM * 32 + lrow) * PITCHB + lcolb;
        uint32_t bBase = st + A_BYTES + (warpN * 48 + lrow) * PITCHB + lcolb;
#pragma unroll
        for (int kk = 0; kk < 4; kk++) {
            uint32_t koff = kk * 32;
            uint32_t a[2][4];
            ldsm4(a[0][0], a[0][1], a[0][2], a[0][3], aBase + koff);
            ldsm4(a[1][0], a[1][1], a[1][2], a[1][3], aBase + 16 * PITCHB + koff);
#pragma unroll
            for (int ntp = 0; ntp < 3; ntp++) {
                uint32_t b0, b1, b2, b3;
                ldsm4(b0, b1, b2, b3, bBase + ntp * 16 * PITCHB + koff);
#pragma unroll
                for (int mt = 0; mt < 2; mt++) {
                    mma16816(acc[mt][2 * ntp + 0], a[mt][0], a[mt][1], a[mt][2], a[mt][3], b0, b2);
                    mma16816(acc[mt][2 * ntp + 1], a[mt][0], a[mt][1], a[mt][2], a[mt][3], b1, b3);
                }
            }
        }
    }

    int g = lid >> 2, t = lid & 3;
#pragma unroll
    for (int mt = 0; mt < 2; mt++) {
#pragma unroll
        for (int nt = 0; nt < 6; nt++) {
            int ncol = warpN * 48 + nt * 8 + 2 * t;
            float b0 = sbias[ncol], b1 = sbias[ncol + 1];
            int mA = m0 + warpM * 32 + mt * 16 + g;
            int mB = mA + 8;
            if (mA < cnt) {
                float2 o = make_float2(acc[mt][nt][0] + b0, acc[mt][nt][1] + b1);
                *(float2*)(g_y + (size_t)(seg0 + mA) * HIDDEN + n0 + ncol) = o;
            }
            if (mB < cnt) {
                float2 o = make_float2(acc[mt][nt][2] + b0, acc[mt][nt][3] + b1);
                *(float2*)(g_y + (size_t)(seg0 + mB) * HIDDEN + n0 + ncol) = o;
            }
        }
    }
}

// ---------------- final combine ------------------------------------------------
__global__ void k_combine(float* __restrict__ out) {
    int idx = blockIdx.x * blockDim.x + threadIdx.x;
    const int per_row = HIDDEN / 4;
    if (idx >= NUM_TOKENS * per_row) return;
    int t = idx / per_row;
    int hq = idx - t * per_row;
    int r1 = g_row_of[2 * t + 0];
    int r2 = g_row_of[2 * t + 1];
    float g1 = g_gate_of[2 * t + 0];
    float g2 = g_gate_of[2 * t + 1];
    float4 a = *((const float4*)(g_y + (size_t)r1 * HIDDEN) + hq);
    float4 b = *((const float4*)(g_y + (size_t)r2 * HIDDEN) + hq);
    float4 o;
    o.x = g1 * a.x + g2 * b.x;
    o.y = g1 * a.y + g2 * b.y;
    o.z = g1 * a.z + g2 * b.z;
    o.w = g1 * a.w + g2 * b.w;
    ((float4*)out)[idx] = o;
}

// ---------------- launch ---------------------------------------------------------
extern "C" void kernel_launch(void* const* d_in, const int* in_sizes, int n_in,
                              void* d_out, int out_size)
{
    const float* hs   = (const float*)d_in[0];
    const float* rl   = (const float*)d_in[1];
    const float* w13  = (const float*)d_in[2];
    const float* w2   = (const float*)d_in[3];
    const float* w13b = (const float*)d_in[4];
    const float* w2b  = (const float*)d_in[5];
    float* out = (float*)d_out;

    static bool attr_done = false;
    if (!attr_done) {
        cudaFuncSetAttribute(k_gemm1, cudaFuncAttributeMaxDynamicSharedMemorySize, G1_SMEM);
        cudaFuncSetAttribute(k_gemm2, cudaFuncAttributeMaxDynamicSharedMemorySize, G2_SMEM);
        attr_done = true;
    }

    k_init<<<1, 32>>>();
    k_route<<<(NUM_TOKENS + 255) / 256, 256>>>(rl);
    k_scan<<<1, 1>>>();
    k_scatter<<<(NUM_TOKENS + 255) / 256, 256>>>();

    __half* w13h_ptr = nullptr;  cudaGetSymbolAddress((void**)&w13h_ptr, g_w13h);
    __half* w2h_ptr  = nullptr;  cudaGetSymbolAddress((void**)&w2h_ptr,  g_w2h);
    __half* hsh_ptr  = nullptr;  cudaGetSymbolAddress((void**)&hsh_ptr,  g_hsh);

    {
        size_t n4 = (size_t)NUM_EXPERTS * N1 * HIDDEN / 4;
        k_cvt<<<(unsigned)((n4 + 255) / 256), 256>>>((const float4*)w13, (uint2*)w13h_ptr, n4);
    }
    {
        size_t n4 = (size_t)NUM_EXPERTS * HIDDEN * INTER / 4;
        k_cvt<<<(unsigned)((n4 + 255) / 256), 256>>>((const float4*)w2, (uint2*)w2h_ptr, n4);
    }
    {
        size_t n4 = (size_t)NUM_TOKENS * HIDDEN / 4;
        k_cvt<<<(unsigned)((n4 + 255) / 256), 256>>>((const float4*)hs, (uint2*)hsh_ptr, n4);
    }

    {
        dim3 grid(NT1, MAXTILES);
        k_gemm1<<<grid, 256, G1_SMEM>>>(w13b);
    }
    {
        dim3 grid(NT2, MAXTILES);
        k_gemm2<<<grid, 256, G2_SMEM>>>(w2b);
    }
    {
        int total = NUM_TOKENS * (HIDDEN / 4);
        k_combine<<<(total + 255) / 256, 256>>>(out);
    }
}

// round 8
// speedup vs baseline: 5.9796x; 1.0110x over previous
#include <cuda_runtime.h>
#include <cuda_fp16.h>
#include <cstdint>

#define NUM_TOKENS 4096
#define NUM_EXPERTS 16
#define HIDDEN 2880
#define INTER 2880
#define N1 (2 * INTER)          /* 5760 */
#define ROWS (NUM_TOKENS * 2)   /* 8192 expanded rows */

#define BM 128
#define BN1 64                  /* GEMM1 N tile (per gate/up) */
#define BN2 96                  /* GEMM2 N tile */
#define BK 64                   /* K chunk, halves */
#define NC (HIDDEN / BK)        /* 45 k-iterations */
#define NT1 (INTER / BN1)       /* 45 */
#define NT2 (HIDDEN / BN2)      /* 30 */
#define MAXTILES 80             /* sum ceil(cnt/128) <= 64 + 16 */
#define CVT_SLICES 16           /* extra blockIdx.y slices in GEMM1 that convert w2 */

#define PITCHB 144              /* 64 halves = 128B + 16B pad */
#define A_BYTES (BM * PITCHB)   /* 18432 */
#define B1_BYTES (BN1 * PITCHB) /* 9216 */
#define B2_BYTES (BN2 * PITCHB) /* 13824 */
#define STG1 (A_BYTES + 2 * B1_BYTES)  /* 36864 */
#define STG2 (A_BYTES + B2_BYTES)      /* 32256 */
#define G1_SMEM (1024 + 3 * STG1)      /* 111616 */
#define G2_SMEM (1024 + 3 * STG2)      /* 97792 */

// ---------------- device scratch ----------------------------------------------
__device__ __align__(256) __half g_w13h[(size_t)NUM_EXPERTS * N1 * HIDDEN];
__device__ __align__(256) __half g_w2h[(size_t)NUM_EXPERTS * HIDDEN * INTER];
__device__ __align__(256) __half g_hsh[(size_t)NUM_TOKENS * HIDDEN];
__device__ __align__(256) __half g_acth[(size_t)ROWS * INTER];
__device__ int   g_rowmap[ROWS];
__device__ float g_gate_by_row[ROWS];
__device__ float g_gate_of[NUM_TOKENS * 2];
__device__ int   g_expert_of[NUM_TOKENS * 2];
__device__ int   g_counts[NUM_EXPERTS];
__device__ int   g_offsets[NUM_EXPERTS + 1];
__device__ int   g_cursor[NUM_EXPERTS];
__device__ int   g_ntiles;
__device__ int   g_tile_e[MAXTILES];
__device__ int   g_tile_m0[MAXTILES];

// ---------------- helpers ------------------------------------------------------
__device__ __forceinline__ uint32_t h2u(float a, float b) {
    __half2 h = __floats2half2_rn(a, b);
    return *reinterpret_cast<uint32_t*>(&h);
}
__device__ __forceinline__ uint32_t smem_u32(const void* p) {
    uint32_t a;
    asm("{ .reg .u64 t; cvta.to.shared.u64 t, %1; cvt.u32.u64 %0, t; }"
        : "=r"(a) : "l"(p));
    return a;
}
#define CP16(dst, src) \
    asm volatile("cp.async.cg.shared.global [%0], [%1], 16;" :: "r"(dst), "l"(src))
#define CP_COMMIT() asm volatile("cp.async.commit_group;" ::: "memory")
#define CP_WAIT1()  asm volatile("cp.async.wait_group 1;" ::: "memory")

__device__ __forceinline__ void ldsm4(uint32_t& r0, uint32_t& r1, uint32_t& r2,
                                      uint32_t& r3, uint32_t addr) {
    asm volatile("ldmatrix.sync.aligned.m8n8.x4.shared.b16 {%0,%1,%2,%3}, [%4];"
                 : "=r"(r0), "=r"(r1), "=r"(r2), "=r"(r3) : "r"(addr));
}
__device__ __forceinline__ void mma16816(float* c, uint32_t a0, uint32_t a1,
                                         uint32_t a2, uint32_t a3,
                                         uint32_t b0, uint32_t b1) {
    asm volatile(
        "mma.sync.aligned.m16n8k16.row.col.f32.f16.f16.f32 "
        "{%0,%1,%2,%3}, {%4,%5,%6,%7}, {%8,%9}, {%0,%1,%2,%3};"
        : "+f"(c[0]), "+f"(c[1]), "+f"(c[2]), "+f"(c[3])
        : "r"(a0), "r"(a1), "r"(a2), "r"(a3), "r"(b0), "r"(b1));
}
__device__ __forceinline__ float silu(float x) {
    return x / (1.0f + __expf(-x));
}

// ---------------- routing ----------------------------------------------------
__global__ void k_init() {
    int i = threadIdx.x;
    if (i < NUM_EXPERTS) { g_counts[i] = 0; g_cursor[i] = 0; }
}
__global__ void k_route(const float* __restrict__ logits) {
    int t = blockIdx.x * blockDim.x + threadIdx.x;
    if (t >= NUM_TOKENS) return;
    const float* l = logits + (size_t)t * NUM_EXPERTS;
    float v[NUM_EXPERTS];
#pragma unroll
    for (int e = 0; e < NUM_EXPERTS; e++) v[e] = l[e];
    int i1 = 0; float v1 = v[0];
#pragma unroll
    for (int e = 1; e < NUM_EXPERTS; e++) if (v[e] > v1) { v1 = v[e]; i1 = e; }
    int i2 = -1; float v2 = -1e30f;
#pragma unroll
    for (int e = 0; e < NUM_EXPERTS; e++)
        if (e != i1 && v[e] > v2) { v2 = v[e]; i2 = e; }
    float g1 = 1.0f / (1.0f + expf(v2 - v1));
    g_expert_of[2 * t + 0] = i1;  g_gate_of[2 * t + 0] = g1;
    g_expert_of[2 * t + 1] = i2;  g_gate_of[2 * t + 1] = 1.0f - g1;
    atomicAdd(&g_counts[i1], 1);
    atomicAdd(&g_counts[i2], 1);
}
__global__ void k_scan() {
    if (threadIdx.x == 0) {
        int acc = 0;
        for (int e = 0; e < NUM_EXPERTS; e++) { g_offsets[e] = acc; acc += g_counts[e]; }
        g_offsets[NUM_EXPERTS] = acc;
        int nt = 0;
        for (int e = 0; e < NUM_EXPERTS; e++) {
            int cnt = g_counts[e];
            for (int m0 = 0; m0 < cnt; m0 += BM) {
                g_tile_e[nt] = e;
                g_tile_m0[nt] = m0;
                nt++;
            }
        }
        g_ntiles = nt;
    }
}
__global__ void k_scatter() {
    int t = blockIdx.x * blockDim.x + threadIdx.x;
    if (t >= NUM_TOKENS) return;
#pragma unroll
    for (int k = 0; k < 2; k++) {
        int e = g_expert_of[2 * t + k];
        int pos = g_offsets[e] + atomicAdd(&g_cursor[e], 1);
        g_rowmap[pos] = t;
        g_gate_by_row[pos] = g_gate_of[2 * t + k];
    }
}

// ---------------- fp32 -> fp16 / zero-out ---------------------------------------
__global__ void k_cvt(const float4* __restrict__ src, uint2* __restrict__ dst,
                      size_t n4) {
    size_t i = (size_t)blockIdx.x * blockDim.x + threadIdx.x;
    if (i >= n4) return;
    float4 v = src[i];
    uint2 o;
    o.x = h2u(v.x, v.y);
    o.y = h2u(v.z, v.w);
    dst[i] = o;
}
__global__ void k_zero(float4* __restrict__ out) {
    size_t i = (size_t)blockIdx.x * blockDim.x + threadIdx.x;
    if (i < (size_t)NUM_TOKENS * HIDDEN / 4)
        out[i] = make_float4(0.f, 0.f, 0.f, 0.f);
}

// ---------------- GEMM1: act = silu(X@Wg^T+bg) * (X@Wu^T+bu) -------------------
// Extra blockIdx.y slices [MAXTILES, MAXTILES+CVT_SLICES) convert w2 fp32->fp16
// concurrently (GEMM1 does not read g_w2h; GEMM2 runs after this kernel).
__global__ __launch_bounds__(256, 2) void k_gemm1(const float* __restrict__ w13b,
                                                  const float4* __restrict__ w2src) {
    int ty = blockIdx.y;
    int tid = threadIdx.x;

    if (ty >= MAXTILES) {                    // w2 conversion CTA
        const size_t n4 = (size_t)NUM_EXPERTS * HIDDEN * INTER / 4;
        const size_t stride = (size_t)CVT_SLICES * NT1 * 256;
        size_t i = ((size_t)(ty - MAXTILES) * gridDim.x + blockIdx.x) * 256 + tid;
        uint2* dst = (uint2*)g_w2h;
        for (; i < n4; i += stride) {
            float4 v = w2src[i];
            uint2 o;
            o.x = h2u(v.x, v.y);
            o.y = h2u(v.z, v.w);
            dst[i] = o;
        }
        return;
    }
    if (ty >= g_ntiles) return;

    extern __shared__ __align__(128) uint8_t smem[];
    int* stok = (int*)smem;
    float* sbias = (float*)(smem + 512);
    uint32_t sb = smem_u32(smem);
    uint32_t stage0 = sb + 1024;

    int e = g_tile_e[ty];
    int m0 = g_tile_m0[ty];
    int seg0 = g_offsets[e];
    int cnt  = g_offsets[e + 1] - seg0;
    int n0 = blockIdx.x * BN1;
    int wid = tid >> 5, lid = tid & 31;
    int warpM = wid & 3, warpN = wid >> 2;

    if (tid < BM) {
        int m = m0 + tid;
        stok[tid] = g_rowmap[seg0 + (m < cnt ? m : cnt - 1)];
    }
    if (tid >= 128 && tid < 192)
        sbias[tid - 128] = w13b[(size_t)e * N1 + n0 + (tid - 128)];
    else if (tid >= 192)
        sbias[tid - 192 + 64] = w13b[(size_t)e * N1 + INTER + n0 + (tid - 192)];
    __syncthreads();

    const __half* wg = g_w13h + (size_t)e * N1 * HIDDEN + (size_t)n0 * HIDDEN;
    const __half* wu = g_w13h + (size_t)e * N1 * HIDDEN + (size_t)(INTER + n0) * HIDDEN;

    auto load_stage = [&](int s, int c) {
        uint32_t st = stage0 + s * STG1;
        int k0 = c * BK;
#pragma unroll
        for (int q = 0; q < 8; q++) {
            int ch = tid + q * 256;          // 0..2047
            if (ch < 1024) {                 // A: 128 rows x 8 chunks of 16B
                int r = ch >> 3, c8 = ch & 7;
                const __half* src = g_hsh + (size_t)stok[r] * HIDDEN + k0 + c8 * 8;
                CP16(st + r * PITCHB + c8 * 16, src);
            } else if (ch < 1536) {          // Bg: 64 rows x 8
                int i = ch - 1024, r = i >> 3, c8 = i & 7;
                const __half* src = wg + (size_t)r * HIDDEN + k0 + c8 * 8;
                CP16(st + A_BYTES + r * PITCHB + c8 * 16, src);
            } else {                         // Bu
                int i = ch - 1536, r = i >> 3, c8 = i & 7;
                const __half* src = wu + (size_t)r * HIDDEN + k0 + c8 * 8;
                CP16(st + A_BYTES + B1_BYTES + r * PITCHB + c8 * 16, src);
            }
        }
        CP_COMMIT();
    };

    float accG[2][4][4], accU[2][4][4];
#pragma unroll
    for (int i = 0; i < 2; i++)
#pragma unroll
        for (int j = 0; j < 4; j++)
#pragma unroll
            for (int q = 0; q < 4; q++) { accG[i][j][q] = 0.f; accU[i][j][q] = 0.f; }

    load_stage(0, 0);
    load_stage(1, 1);

    int lrow = lid & 15;
    int lcolb = (lid & 16);                  // 0 or 16 bytes

    for (int c = 0; c < NC; c++) {
        CP_WAIT1();
        __syncthreads();
        if (c + 2 < NC) load_stage((c + 2) % 3, c + 2);
        else CP_COMMIT();                    // keep group ledger advancing (tail)
        uint32_t st = stage0 + (c % 3) * STG1;
        uint32_t aBase = st + (warpM * 32 + lrow) * PITCHB + lcolb;
        uint32_t gBase = st + A_BYTES + (warpN * 32 + lrow) * PITCHB + lcolb;
        uint32_t uBase = gBase + B1_BYTES;
#pragma unroll
        for (int kk = 0; kk < 4; kk++) {     // four k16 steps
            uint32_t koff = kk * 32;
            uint32_t a[2][4];
            ldsm4(a[0][0], a[0][1], a[0][2], a[0][3], aBase + koff);
            ldsm4(a[1][0], a[1][1], a[1][2], a[1][3], aBase + 16 * PITCHB + koff);
#pragma unroll
            for (int ntp = 0; ntp < 2; ntp++) {
                uint32_t b0, b1, b2, b3;
                ldsm4(b0, b1, b2, b3, gBase + ntp * 16 * PITCHB + koff);
#pragma unroll
                for (int mt = 0; mt < 2; mt++) {
                    mma16816(accG[mt][2 * ntp + 0], a[mt][0], a[mt][1], a[mt][2], a[mt][3], b0, b2);
                    mma16816(accG[mt][2 * ntp + 1], a[mt][0], a[mt][1], a[mt][2], a[mt][3], b1, b3);
                }
                ldsm4(b0, b1, b2, b3, uBase + ntp * 16 * PITCHB + koff);
#pragma unroll
                for (int mt = 0; mt < 2; mt++) {
                    mma16816(accU[mt][2 * ntp + 0], a[mt][0], a[mt][1], a[mt][2], a[mt][3], b0, b2);
                    mma16816(accU[mt][2 * ntp + 1], a[mt][0], a[mt][1], a[mt][2], a[mt][3], b1, b3);
                }
            }
        }
    }

    int g = lid >> 2, t = lid & 3;
#pragma unroll
    for (int mt = 0; mt < 2; mt++) {
#pragma unroll
        for (int nt = 0; nt < 4; nt++) {
            int ncol = warpN * 32 + nt * 8 + 2 * t;
            float bg0 = sbias[ncol], bg1 = sbias[ncol + 1];
            float bu0 = sbias[64 + ncol], bu1 = sbias[64 + ncol + 1];
            int mA = m0 + warpM * 32 + mt * 16 + g;
            int mB = mA + 8;
            if (mA < cnt) {
                float a0 = silu(accG[mt][nt][0] + bg0) * (accU[mt][nt][0] + bu0);
                float a1 = silu(accG[mt][nt][1] + bg1) * (accU[mt][nt][1] + bu1);
                *(uint32_t*)(g_acth + (size_t)(seg0 + mA) * INTER + n0 + ncol) = h2u(a0, a1);
            }
            if (mB < cnt) {
                float a2 = silu(accG[mt][nt][2] + bg0) * (accU[mt][nt][2] + bu0);
                float a3 = silu(accG[mt][nt][3] + bg1) * (accU[mt][nt][3] + bu1);
                *(uint32_t*)(g_acth + (size_t)(seg0 + mB) * INTER + n0 + ncol) = h2u(a2, a3);
            }
        }
    }
}

// ---------------- GEMM2: out += gate * (act @ W2^T + b2), fused combine --------
__global__ __launch_bounds__(256, 2) void k_gemm2(const float* __restrict__ w2b,
                                                  float* __restrict__ out) {
    extern __shared__ __align__(128) uint8_t smem[];
    float* sbias = (float*)(smem + 512);
    uint32_t sb = smem_u32(smem);
    uint32_t stage0 = sb + 1024;

    int ty = blockIdx.y;
    if (ty >= g_ntiles) return;
    int e = g_tile_e[ty];
    int m0 = g_tile_m0[ty];
    int seg0 = g_offsets[e];
    int cnt  = g_offsets[e + 1] - seg0;
    int n0 = blockIdx.x * BN2;
    int tid = threadIdx.x, wid = tid >> 5, lid = tid & 31;
    int warpM = wid & 3, warpN = wid >> 2;

    if (tid < BN2) sbias[tid] = w2b[(size_t)e * HIDDEN + n0 + tid];
    __syncthreads();

    const __half* wb = g_w2h + (size_t)e * HIDDEN * INTER + (size_t)n0 * INTER;
    const __half* aext = g_acth + (size_t)seg0 * INTER;
    int mclamp = cnt - 1;

    auto load_stage = [&](int s, int c) {
        uint32_t st = stage0 + s * STG2;
        int k0 = c * BK;
#pragma unroll
        for (int q = 0; q < 7; q++) {
            int ch = tid + q * 256;          // 0..1791
            if (ch < 1024) {                 // A: 128 rows x 8
                int r = ch >> 3, c8 = ch & 7;
                int m = m0 + r; if (m > mclamp) m = mclamp;
                const __half* src = aext + (size_t)m * INTER + k0 + c8 * 8;
                CP16(st + r * PITCHB + c8 * 16, src);
            } else {                         // B: 96 rows x 8
                int i = ch - 1024, r = i >> 3, c8 = i & 7;
                const __half* src = wb + (size_t)r * INTER + k0 + c8 * 8;
                CP16(st + A_BYTES + r * PITCHB + c8 * 16, src);
            }
        }
        CP_COMMIT();
    };

    float acc[2][6][4];
#pragma unroll
    for (int i = 0; i < 2; i++)
#pragma unroll
        for (int j = 0; j < 6; j++)
#pragma unroll
            for (int q = 0; q < 4; q++) acc[i][j][q] = 0.f;

    load_stage(0, 0);
    load_stage(1, 1);

    int lrow = lid & 15;
    int lcolb = (lid & 16);

    for (int c = 0; c < NC; c++) {
        CP_WAIT1();
        __syncthreads();
        if (c + 2 < NC) load_stage((c + 2) % 3, c + 2);
        else CP_COMMIT();                    // keep group ledger advancing (tail)
        uint32_t st = stage0 + (c % 3) * STG2;
        uint32_t aBase = st + (warpM * 32 + lrow) * PITCHB + lcolb;
        uint32_t bBase = st + A_BYTES + (warpN * 48 + lrow) * PITCHB + lcolb;
#pragma unroll
        for (int kk = 0; kk < 4; kk++) {
            uint32_t koff = kk * 32;
            uint32_t a[2][4];
            ldsm4(a[0][0], a[0][1], a[0][2], a[0][3], aBase + koff);
            ldsm4(a[1][0], a[1][1], a[1][2], a[1][3], aBase + 16 * PITCHB + koff);
#pragma unroll
            for (int ntp = 0; ntp < 3; ntp++) {
                uint32_t b0, b1, b2, b3;
                ldsm4(b0, b1, b2, b3, bBase + ntp * 16 * PITCHB + koff);
#pragma unroll
                for (int mt = 0; mt < 2; mt++) {
                    mma16816(acc[mt][2 * ntp + 0], a[mt][0], a[mt][1], a[mt][2], a[mt][3], b0, b2);
                    mma16816(acc[mt][2 * ntp + 1], a[mt][0], a[mt][1], a[mt][2], a[mt][3], b1, b3);
                }
            }
        }
    }

    // fused combine epilogue: out[token] += gate * (acc + bias)
    int g = lid >> 2, t = lid & 3;
#pragma unroll
    for (int mt = 0; mt < 2; mt++) {
        int mA = m0 + warpM * 32 + mt * 16 + g;
        int mB = mA + 8;
        int tokA = 0, tokB = 0;
        float gA = 0.f, gB = 0.f;
        if (mA < cnt) { tokA = g_rowmap[seg0 + mA]; gA = g_gate_by_row[seg0 + mA]; }
        if (mB < cnt) { tokB = g_rowmap[seg0 + mB]; gB = g_gate_by_row[seg0 + mB]; }
#pragma unroll
        for (int nt = 0; nt < 6; nt++) {
            int ncol = warpN * 48 + nt * 8 + 2 * t;
            float b0 = sbias[ncol], b1 = sbias[ncol + 1];
            if (mA < cnt) {
                float* d = out + (size_t)tokA * HIDDEN + n0 + ncol;
                atomicAdd(d + 0, gA * (acc[mt][nt][0] + b0));
                atomicAdd(d + 1, gA * (acc[mt][nt][1] + b1));
            }
            if (mB < cnt) {
                float* d = out + (size_t)tokB * HIDDEN + n0 + ncol;
                atomicAdd(d + 0, gB * (acc[mt][nt][2] + b0));
                atomicAdd(d + 1, gB * (acc[mt][nt][3] + b1));
            }
        }
    }
}

// ---------------- launch ---------------------------------------------------------
extern "C" void kernel_launch(void* const* d_in, const int* in_sizes, int n_in,
                              void* d_out, int out_size)
{
    const float* hs   = (const float*)d_in[0];
    const float* rl   = (const float*)d_in[1];
    const float* w13  = (const float*)d_in[2];
    const float* w2   = (const float*)d_in[3];
    const float* w13b = (const float*)d_in[4];
    const float* w2b  = (const float*)d_in[5];
    float* out = (float*)d_out;

    static bool attr_done = false;
    if (!attr_done) {
        cudaFuncSetAttribute(k_gemm1, cudaFuncAttributeMaxDynamicSharedMemorySize, G1_SMEM);
        cudaFuncSetAttribute(k_gemm2, cudaFuncAttributeMaxDynamicSharedMemorySize, G2_SMEM);
        attr_done = true;
    }

    k_init<<<1, 32>>>();
    k_route<<<(NUM_TOKENS + 255) / 256, 256>>>(rl);
    k_scan<<<1, 1>>>();
    k_scatter<<<(NUM_TOKENS + 255) / 256, 256>>>();

    {
        size_t n4 = (size_t)NUM_TOKENS * HIDDEN / 4;
        k_zero<<<(unsigned)((n4 + 255) / 256), 256>>>((float4*)out);
    }

    __half* w13h_ptr = nullptr;  cudaGetSymbolAddress((void**)&w13h_ptr, g_w13h);
    __half* hsh_ptr  = nullptr;  cudaGetSymbolAddress((void**)&hsh_ptr,  g_hsh);

    {
        size_t n4 = (size_t)NUM_EXPERTS * N1 * HIDDEN / 4;
        k_cvt<<<(unsigned)((n4 + 255) / 256), 256>>>((const float4*)w13, (uint2*)w13h_ptr, n4);
    }
    {
        size_t n4 = (size_t)NUM_TOKENS * HIDDEN / 4;
        k_cvt<<<(unsigned)((n4 + 255) / 256), 256>>>((const float4*)hs, (uint2*)hsh_ptr, n4);
    }

    {   // GEMM1 + concurrent w2 conversion (extra y-slices)
        dim3 grid(NT1, MAXTILES + CVT_SLICES);
        k_gemm1<<<grid, 256, G1_SMEM>>>(w13b, (const float4*)w2);
    }
    {   // GEMM2 with fused gate-combine into out
        dim3 grid(NT2, MAXTILES);
        k_gemm2<<<grid, 256, G2_SMEM>>>(w2b, out);
    }
}